// round 13
// baseline (speedup 1.0000x reference)
#include <cuda_runtime.h>
#include <cuda_bf16.h>
#include <math.h>

#define NN 50000
#define EE 1600000
#define TT 12
#define FF 16
#define HH 128
#define OUTD 3
#define HOR 6

#define KTOT 144            // 128 (h) + 16 (agg)
#define ASTRIDE 152         // bf16 units per row (304 B) -> conflict-free ldmatrix
#define ROWB (ASTRIDE * 2)  // 304 bytes

// smem layout (bytes)
#define OFF_AHI 0
#define OFF_ALO 38912
#define OFF_BHI 77824
#define OFF_BLO 116736
#define OFF_HS  155648      // hs fp32 [128][129]
#define SMEM_CELL (155648 + 128 * 129 * 4)   // 221696

#define THR_CELL 512

// ---------------- scratch ----------------
__device__ float g_dinv_all[TT * NN];
__device__ float g_agg_all[(size_t)TT * NN * FF];
__device__ float g_aggh[2 * NN * FF];
__device__ float g_nrm11[EE];
__device__ float g_h[NN * HH];
__device__ float g_hw[NN * HH];
__device__ unsigned char g_maskc[TT * NN];
__device__ unsigned char g_meff[TT * NN];
__device__ float g_Bzr_top[16 * 256];
__device__ float g_bzr[256];
__device__ float g_Bzr_bot[128 * 256];
__device__ float g_Bh_top[16 * 128];
__device__ float g_bh[128];
__device__ int g_isbyte;
// bf16 weight splits, [n][ASTRIDE] row-major (k contiguous), per gate {z,r,h}
__device__ __align__(16) unsigned short g_Bsp_hi[3][128 * ASTRIDE];
__device__ __align__(16) unsigned short g_Bsp_lo[3][128 * ASTRIDE];

// ---------------- helpers ----------------
__device__ __forceinline__ unsigned int s2u(const void* p) {
    unsigned int a;
    asm("{ .reg .u64 t; cvta.to.shared.u64 t, %1; cvt.u32.u64 %0, t; }"
        : "=r"(a) : "l"(p));
    return a;
}
__device__ __forceinline__ float bfr(float x) {
    return __bfloat162float(__float2bfloat16_rn(x));
}
__device__ __forceinline__ unsigned int pkbf(float lo, float hi) {  // lo -> low half
    unsigned int r;
    asm("cvt.rn.bf16x2.f32 %0, %1, %2;" : "=r"(r) : "f"(hi), "f"(lo));
    return r;
}
__device__ __forceinline__ void ldm4(unsigned int* r, unsigned int addr) {
    asm volatile("ldmatrix.sync.aligned.m8n8.x4.shared.b16 {%0,%1,%2,%3}, [%4];"
        : "=r"(r[0]), "=r"(r[1]), "=r"(r[2]), "=r"(r[3]) : "r"(addr));
}
__device__ __forceinline__ void mma_bf(float* d, const unsigned int* a,
                                       const unsigned int* b) {
    asm volatile(
        "mma.sync.aligned.m16n8k16.row.col.f32.bf16.bf16.f32 "
        "{%0,%1,%2,%3}, {%4,%5,%6,%7}, {%8,%9}, {%0,%1,%2,%3};"
        : "+f"(d[0]), "+f"(d[1]), "+f"(d[2]), "+f"(d[3])
        : "r"(a[0]), "r"(a[1]), "r"(a[2]), "r"(a[3]), "r"(b[0]), "r"(b[1]));
}
__device__ __forceinline__ float sigmoidf_(float v) {
    return 1.0f / (1.0f + __expf(-v));
}

// ---------------- mask detection / conversion ----------------
__global__ void k_detect(const unsigned char* raw) {
    __shared__ int cnt;
    if (threadIdx.x == 0) cnt = 0;
    __syncthreads();
    int c = 0;
    for (int i = threadIdx.x; i < 4096; i += blockDim.x) c += (raw[i] != 0);
    atomicAdd(&cnt, c);
    __syncthreads();
    if (threadIdx.x == 0) g_isbyte = (cnt > 2048) ? 1 : 0;
}
__global__ void k_convert(const unsigned char* raw) {
    int n = blockIdx.x * blockDim.x + threadIdx.x;
    if (n >= NN) return;
    int isb = g_isbyte, seen = 0;
#pragma unroll
    for (int t = 0; t < TT; ++t) {
        int m = isb ? (raw[t * NN + n] != 0) : (((const int*)raw)[t * NN + n] != 0);
        g_maskc[t * NN + n] = (unsigned char)m;
        g_meff[t * NN + n] = (unsigned char)(m & seen);
        seen |= m;
    }
}

// ---------------- weight fusion ----------------
__global__ void k_fuse(const float* __restrict__ Wcz, const float* __restrict__ Wlz,
                       const float* __restrict__ blz, const float* __restrict__ bcz,
                       const float* __restrict__ Wcr, const float* __restrict__ Wlr,
                       const float* __restrict__ blr, const float* __restrict__ bcr,
                       const float* __restrict__ Wch, const float* __restrict__ Wlh,
                       const float* __restrict__ blh, const float* __restrict__ bch) {
    int i = blockIdx.x * blockDim.x + threadIdx.x;
    if (i < 16 * 256) {
        int k = i / 256, c = i % 256, cc = c & 127;
        const float* A = (c < 128) ? Wcz : Wcr;
        const float* B = (c < 128) ? Wlz : Wlr;
        float s = 0.f;
        for (int j = 0; j < 128; ++j) s += A[k * 128 + j] * B[j * 128 + cc];
        g_Bzr_top[i] = s;
    } else if (i < 4096 + 2048) {
        int r = i - 4096; int k = r / 128, c = r % 128;
        float s = 0.f;
        for (int j = 0; j < 128; ++j) s += Wch[k * 128 + j] * Wlh[j * 128 + c];
        g_Bh_top[r] = s;
    } else if (i < 6144 + 256) {
        int c = i - 6144; int cc = c & 127;
        const float* bc = (c < 128) ? bcz : bcr;
        const float* B  = (c < 128) ? Wlz : Wlr;
        const float* bl = (c < 128) ? blz : blr;
        float s = bl[cc];
        for (int j = 0; j < 128; ++j) s += bc[j] * B[j * 128 + cc];
        g_bzr[c] = s;
    } else if (i < 6400 + 128) {
        int c = i - 6400;
        float s = blh[c];
        for (int j = 0; j < 128; ++j) s += bch[j] * Wlh[j * 128 + c];
        g_bh[c] = s;
    } else if (i < 6528 + 128 * 256) {
        int r = i - 6528; int k = r / 256, c = r % 256;
        g_Bzr_bot[r] = (c < 128) ? Wlz[(128 + k) * 128 + c]
                                 : Wlr[(128 + k) * 128 + (c - 128)];
    }
}

// bf16 hi/lo splits: B[n][k] = W[k][n]; k 0..127 = bottom, 128..143 = top
__global__ void k_fuse2(const float* __restrict__ Wlh_bot) {
    int i = blockIdx.x * blockDim.x + threadIdx.x;
    if (i >= 3 * KTOT * 128) return;
    int g = i / (KTOT * 128), r = i - g * (KTOT * 128);
    int k = r / 128, n = r - k * 128;
    float w;
    if (k < 128) {
        if (g == 0)      w = g_Bzr_bot[k * 256 + n];
        else if (g == 1) w = g_Bzr_bot[k * 256 + 128 + n];
        else             w = Wlh_bot[k * 128 + n];
    } else {
        int kt = k - 128;
        if (g == 0)      w = g_Bzr_top[kt * 256 + n];
        else if (g == 1) w = g_Bzr_top[kt * 256 + 128 + n];
        else             w = g_Bh_top[kt * 128 + n];
    }
    float wh = bfr(w);
    g_Bsp_hi[g][n * ASTRIDE + k] = __bfloat16_as_ushort(__float2bfloat16_rn(wh));
    g_Bsp_lo[g][n * ASTRIDE + k] = __bfloat16_as_ushort(__float2bfloat16_rn(w - wh));
}

__global__ void k_init() {
    int i = blockIdx.x * blockDim.x + threadIdx.x;
    if (i < NN * HH) g_h[i] = 0.f;
    if (i < TT * NN) g_dinv_all[i] = 0.f;
}

// ---------------- degree / aggregation (t-ranged for stream overlap) ----------------
__global__ void k_deg_rng(const int* __restrict__ ei, const float* __restrict__ ea,
                          int t0, int nt) {
    int e = blockIdx.x * blockDim.x + threadIdx.x;
    if (e >= nt * EE) return;
    int t = t0 + e / EE, le = e % EE;
    int dst = ei[(size_t)t * 2 * EE + EE + le];
    atomicAdd(&g_dinv_all[t * NN + dst], ea[(size_t)t * EE + le]);
}
__global__ void k_dinv_rng(int t0, int nt) {
    int i = blockIdx.x * blockDim.x + threadIdx.x;
    if (i >= nt * NN) return;
    int idx = t0 * NN + i;
    g_dinv_all[idx] = rsqrtf(g_dinv_all[idx] + 1.0f);
}
__global__ void k_aggself_rng(const float* __restrict__ x_seq, int t0, int nt) {
    int i = blockIdx.x * blockDim.x + threadIdx.x;
    if (i >= nt * NN) return;
    int t = t0 + i / NN, n = i % NN;
    float di = g_dinv_all[t * NN + n];
    float s = di * di;
    const float4* xp = (const float4*)(x_seq + (size_t)t * NN * FF + (size_t)n * FF);
    float4* op = (float4*)(g_agg_all + (size_t)t * NN * FF + (size_t)n * FF);
    float4 a = xp[0], b = xp[1], c = xp[2], d = xp[3];
    op[0] = make_float4(s * a.x, s * a.y, s * a.z, s * a.w);
    op[1] = make_float4(s * b.x, s * b.y, s * b.z, s * b.w);
    op[2] = make_float4(s * c.x, s * c.y, s * c.z, s * c.w);
    op[3] = make_float4(s * d.x, s * d.y, s * d.z, s * d.w);
}
#define REDV4(p, a, b, c, d)                                              \
    asm volatile("red.global.add.v4.f32 [%0], {%1,%2,%3,%4};"             \
                 :: "l"(p), "f"(a), "f"(b), "f"(c), "f"(d) : "memory")
#define REDV2(p, a, b)                                                    \
    asm volatile("red.global.add.v2.f32 [%0], {%1,%2};"                   \
                 :: "l"(p), "f"(a), "f"(b) : "memory")
#define RED1(p, a)                                                        \
    asm volatile("red.global.add.f32 [%0], %1;"                           \
                 :: "l"(p), "f"(a) : "memory")
__global__ void k_scatter_one(const int* __restrict__ ei, const float* __restrict__ ea,
                              const float* __restrict__ x_seq, int t) {
    int le = blockIdx.x * blockDim.x + threadIdx.x;
    if (le >= EE) return;
    const int* eit = ei + (size_t)t * 2 * EE;
    int s = eit[le], d = eit[EE + le];
    const float* dinv = g_dinv_all + t * NN;
    float nrm = dinv[s] * ea[(size_t)t * EE + le] * dinv[d];
    if (t == 11) g_nrm11[le] = nrm;
    const float4* xp = (const float4*)(x_seq + (size_t)t * NN * FF + (size_t)s * FF);
    float4 a = xp[0], b = xp[1], c = xp[2], dd = xp[3];
    float* o = g_agg_all + (size_t)t * NN * FF + (size_t)d * FF;
    REDV4(o + 0,  nrm * a.x,  nrm * a.y,  nrm * a.z,  nrm * a.w);
    REDV4(o + 4,  nrm * b.x,  nrm * b.y,  nrm * b.z,  nrm * b.w);
    REDV4(o + 8,  nrm * c.x,  nrm * c.y,  nrm * c.z,  nrm * c.w);
    REDV4(o + 12, nrm * dd.x, nrm * dd.y, nrm * dd.z, nrm * dd.w);
}

// ---------------- fused TGCN cell: mma.sync bf16 split GEMMs ----------------
// flags: bit0 = horizon, bit1 = write g_hw = mk ? hn : 0 (t==11), bit2 = h_eff==0
__global__ __launch_bounds__(THR_CELL, 1)
void k_cell(const float* __restrict__ agg, int t, int flags,
            const float* __restrict__ headW, const float* __restrict__ headb,
            float* __restrict__ outk, float* __restrict__ agghN) {
    extern __shared__ __align__(16) char smc[];
    char*  Ahi = smc + OFF_AHI;
    char*  Alo = smc + OFF_ALO;
    char*  Bhi = smc + OFF_BHI;
    char*  Blo = smc + OFF_BLO;
    float* hs  = (float*)(smc + OFF_HS);
    unsigned int sbase = s2u(smc);

    const int tid = threadIdx.x;
    const int nblk = blockIdx.x * 128;
    const bool horizon = (flags & 1) != 0;
    const bool wrHw = (flags & 2) != 0;
    const bool hz = (flags & 4) != 0;
    const float* hsrc = horizon ? g_hw : g_h;
    const unsigned char* me = g_meff + (size_t)t * NN;
    const unsigned char* mk = g_maskc + (size_t)t * NN;

    const int w = tid >> 5, l = tid & 31;
    const int m0 = (w & 3) * 32, n0 = (w >> 2) * 32;
    const int fg = l >> 2, fc = l & 3;

    // ---- staging: A (h split + agg split), hs fp32, B gate-z ----
    {
        int row = tid >> 2, q = tid & 3;
        int nA = nblk + row;
        bool rowValid = nA < NN;
        bool rowOn = rowValid && (horizon || (me[nA] != 0));
        char* arow_h = Ahi + row * ROWB;
        char* arow_l = Alo + row * ROWB;
#pragma unroll
        for (int g8 = 0; g8 < 8; ++g8) {
            int k0 = q * 32 + g8 * 4;
            float4 v = make_float4(0.f, 0.f, 0.f, 0.f);
            if (rowOn) v = *(const float4*)(hsrc + (size_t)nA * HH + k0);
            hs[row * 129 + k0 + 0] = v.x;
            hs[row * 129 + k0 + 1] = v.y;
            hs[row * 129 + k0 + 2] = v.z;
            hs[row * 129 + k0 + 3] = v.w;
            float xh = bfr(v.x), yh = bfr(v.y), zh = bfr(v.z), wh = bfr(v.w);
            *(unsigned int*)(arow_h + k0 * 2)     = pkbf(xh, yh);
            *(unsigned int*)(arow_h + k0 * 2 + 4) = pkbf(zh, wh);
            *(unsigned int*)(arow_l + k0 * 2)     = pkbf(v.x - xh, v.y - yh);
            *(unsigned int*)(arow_l + k0 * 2 + 4) = pkbf(v.z - zh, v.w - wh);
        }
        {
            float4 v = make_float4(0.f, 0.f, 0.f, 0.f);
            if (rowValid) v = *(const float4*)(agg + (size_t)nA * 16 + 4 * q);
            int kb = (128 + q * 4) * 2;
            float xh = bfr(v.x), yh = bfr(v.y), zh = bfr(v.z), wh = bfr(v.w);
            *(unsigned int*)(arow_h + kb)     = pkbf(xh, yh);
            *(unsigned int*)(arow_h + kb + 4) = pkbf(zh, wh);
            *(unsigned int*)(arow_l + kb)     = pkbf(v.x - xh, v.y - yh);
            *(unsigned int*)(arow_l + kb + 4) = pkbf(v.z - zh, v.w - wh);
        }
        const float4* sh = (const float4*)g_Bsp_hi[0];
        const float4* sl = (const float4*)g_Bsp_lo[0];
        float4* dh = (float4*)Bhi;
        float4* dl = (float4*)Blo;
        for (int i = tid; i < 128 * ASTRIDE / 8; i += THR_CELL) {
            dh[i] = sh[i]; dl[i] = sl[i];
        }
    }
    __syncthreads();

    unsigned int aHiAd = sbase + OFF_AHI + (m0 + (l & 15)) * ROWB + (l >> 4) * 16;
    unsigned int aLoAd = aHiAd + (OFF_ALO - OFF_AHI);
    unsigned int bHiAd = sbase + OFF_BHI +
                         (n0 + (l >> 4) * 8 + (l & 7)) * ROWB + ((l >> 3) & 1) * 16;
    unsigned int bLoAd = bHiAd + (OFF_BLO - OFF_BHI);
    const int kt0 = hz ? 8 : 0;

    float dd[32];
    float zreg[32];

#define GATE_MMA()                                                          \
    _Pragma("unroll") for (int j = 0; j < 32; ++j) dd[j] = 0.f;             \
    for (int kt = kt0; kt < 9; ++kt) {                                      \
        unsigned int ah[2][4], al[2][4], bh[2][4], bl[2][4];                \
        ldm4(ah[0], aHiAd + kt * 32);                                       \
        ldm4(ah[1], aHiAd + kt * 32 + 16 * ROWB);                           \
        ldm4(al[0], aLoAd + kt * 32);                                       \
        ldm4(al[1], aLoAd + kt * 32 + 16 * ROWB);                           \
        ldm4(bh[0], bHiAd + kt * 32);                                       \
        ldm4(bh[1], bHiAd + kt * 32 + 16 * ROWB);                           \
        ldm4(bl[0], bLoAd + kt * 32);                                       \
        ldm4(bl[1], bLoAd + kt * 32 + 16 * ROWB);                           \
        _Pragma("unroll") for (int am = 0; am < 2; ++am)                    \
        _Pragma("unroll") for (int bn = 0; bn < 4; ++bn) {                  \
            float* dp = dd + (am * 4 + bn) * 4;                             \
            const unsigned int* bhp = &bh[bn >> 1][(bn & 1) * 2];           \
            const unsigned int* blp = &bl[bn >> 1][(bn & 1) * 2];           \
            mma_bf(dp, ah[am], bhp);                                        \
            mma_bf(dp, ah[am], blp);                                        \
            mma_bf(dp, al[am], bhp);                                        \
        }                                                                   \
    }

    // ================= gate Z =================
    GATE_MMA();
#pragma unroll
    for (int am = 0; am < 2; ++am)
#pragma unroll
    for (int bn = 0; bn < 4; ++bn)
#pragma unroll
    for (int e = 0; e < 4; ++e) {
        int idx = (am * 4 + bn) * 4 + e;
        int col = n0 + 8 * bn + 2 * fc + (e & 1);
        zreg[idx] = sigmoidf_(dd[idx] + g_bzr[col]);
    }
    __syncthreads();
    {
        const float4* sh = (const float4*)g_Bsp_hi[1];
        const float4* sl = (const float4*)g_Bsp_lo[1];
        float4* dh = (float4*)Bhi;
        float4* dl = (float4*)Blo;
        for (int i = tid; i < 128 * ASTRIDE / 8; i += THR_CELL) {
            dh[i] = sh[i]; dl[i] = sl[i];
        }
    }
    __syncthreads();

    // ================= gate R =================
    GATE_MMA();
#pragma unroll
    for (int am = 0; am < 2; ++am)
#pragma unroll
    for (int bn = 0; bn < 4; ++bn)
#pragma unroll
    for (int eh = 0; eh < 2; ++eh) {
        int idx = (am * 4 + bn) * 4 + eh * 2;
        int row = m0 + 16 * am + fg + eh * 8;
        int cb = n0 + 8 * bn + 2 * fc;
        float r0 = sigmoidf_(dd[idx]     + g_bzr[128 + cb]);
        float r1 = sigmoidf_(dd[idx + 1] + g_bzr[128 + cb + 1]);
        if (!hz) {
            float p0 = hs[row * 129 + cb] * r0;
            float p1 = hs[row * 129 + cb + 1] * r1;
            float p0h = bfr(p0), p1h = bfr(p1);
            *(unsigned int*)(Ahi + row * ROWB + cb * 2) = pkbf(p0h, p1h);
            *(unsigned int*)(Alo + row * ROWB + cb * 2) = pkbf(p0 - p0h, p1 - p1h);
        }
    }
    __syncthreads();
    {
        const float4* sh = (const float4*)g_Bsp_hi[2];
        const float4* sl = (const float4*)g_Bsp_lo[2];
        float4* dh = (float4*)Bhi;
        float4* dl = (float4*)Blo;
        for (int i = tid; i < 128 * ASTRIDE / 8; i += THR_CELL) {
            dh[i] = sh[i]; dl[i] = sl[i];
        }
    }
    __syncthreads();

    // ================= gate H + combine =================
    GATE_MMA();
#pragma unroll
    for (int am = 0; am < 2; ++am)
#pragma unroll
    for (int bn = 0; bn < 4; ++bn)
#pragma unroll
    for (int e = 0; e < 4; ++e) {
        int idx = (am * 4 + bn) * 4 + e;
        int row = m0 + 16 * am + fg + (e >> 1) * 8;
        int col = n0 + 8 * bn + 2 * fc + (e & 1);
        float ht = tanhf(dd[idx] + g_bh[col]);
        float z = zreg[idx];
        float h0 = hs[row * 129 + col];
        hs[row * 129 + col] = z * h0 + (1.f - z) * ht;
    }
    __syncthreads();

    if (horizon && tid < 96) {
        float4 wv = *(const float4*)(headW + tid * 4);
        ((float*)Bhi)[tid * 4 + 0] = wv.x; ((float*)Bhi)[tid * 4 + 1] = wv.y;
        ((float*)Bhi)[tid * 4 + 2] = wv.z; ((float*)Bhi)[tid * 4 + 3] = wv.w;
    }

    // ---- coalesced masked writeback ----
    {
        int row = tid >> 2, cg = (tid & 3) * 32;
        int n = nblk + row;
        if (n < NN) {
            bool wr = horizon ? true : (mk[n] != 0);
#pragma unroll
            for (int i4 = 0; i4 < 8; ++i4) {
                float4 v;
                v.x = hs[row * 129 + cg + 4 * i4 + 0];
                v.y = hs[row * 129 + cg + 4 * i4 + 1];
                v.z = hs[row * 129 + cg + 4 * i4 + 2];
                v.w = hs[row * 129 + cg + 4 * i4 + 3];
                if (horizon) {
                    *(float4*)(g_hw + (size_t)n * HH + cg + 4 * i4) = v;
                } else {
                    if (wr) *(float4*)(g_h + (size_t)n * HH + cg + 4 * i4) = v;
                    if (wrHw) {
                        float4 vz = wr ? v : make_float4(0.f, 0.f, 0.f, 0.f);
                        *(float4*)(g_hw + (size_t)n * HH + cg + 4 * i4) = vz;
                    }
                }
            }
        }
    }

    // ---- fused head prediction (horizon): 4 threads per node + shfl reduce ----
    if (horizon) {
        __syncthreads();
        int row = tid >> 2, pp = tid & 3;
        int n = nblk + row;
        const float* hwv = (const float*)Bhi;
        float p0 = 0.f, p1 = 0.f, p2 = 0.f;
        int c0 = pp * 32;
#pragma unroll 8
        for (int c = c0; c < c0 + 32; ++c) {
            float hv = hs[row * 129 + c];
            p0 += hv * hwv[c * 3 + 0];
            p1 += hv * hwv[c * 3 + 1];
            p2 += hv * hwv[c * 3 + 2];
        }
#pragma unroll
        for (int o = 2; o >= 1; o >>= 1) {
            p0 += __shfl_down_sync(0xFFFFFFFFu, p0, o, 4);
            p1 += __shfl_down_sync(0xFFFFFFFFu, p1, o, 4);
            p2 += __shfl_down_sync(0xFFFFFFFFu, p2, o, 4);
        }
        if (pp == 0 && n < NN) {
            p0 += headb[0]; p1 += headb[1]; p2 += headb[2];
            outk[n * 3 + 0] = p0;
            outk[n * 3 + 1] = p1;
            outk[n * 3 + 2] = p2;
            float di = g_dinv_all[11 * NN + n];
            float s = di * di;
            agghN[n * FF + 0] = s * p0;
            agghN[n * FF + 1] = s * p1;
            agghN[n * FF + 2] = s * p2;
        }
    }
}

// ---------------- transition / horizon helpers ----------------
__global__ void k_transition(const float* __restrict__ agg11) {
    int i = blockIdx.x * blockDim.x + threadIdx.x;
    if (i >= NN * FF) return;
    float v = agg11[i];
    g_aggh[i] = v;
    g_aggh[NN * FF + i] = v;
}
__global__ void k_scatter3(const int* __restrict__ ei11,
                           const float* __restrict__ pred,
                           float* __restrict__ target) {
    int e = blockIdx.x * blockDim.x + threadIdx.x;
    if (e >= EE) return;
    int s = ei11[e], d = ei11[EE + e];
    float nrm = g_nrm11[e];
    float p0 = pred[s * 3 + 0], p1 = pred[s * 3 + 1], p2 = pred[s * 3 + 2];
    float* o = target + (size_t)d * FF;
    REDV2(o, nrm * p0, nrm * p1);
    RED1(o + 2, nrm * p2);
}

// ---------------- launch ----------------
extern "C" void kernel_launch(void* const* d_in, const int* in_sizes, int n_in,
                              void* d_out, int out_size) {
    const float* x_seq = (const float*)d_in[0];
    const int*   ei    = (const int*)d_in[1];
    const float* ea    = (const float*)d_in[2];
    const unsigned char* mraw = (const unsigned char*)d_in[3];
    const float* Wcz = (const float*)d_in[4];
    const float* bcz = (const float*)d_in[5];
    const float* Wlz = (const float*)d_in[6];
    const float* blz = (const float*)d_in[7];
    const float* Wcr = (const float*)d_in[8];
    const float* bcr = (const float*)d_in[9];
    const float* Wlr = (const float*)d_in[10];
    const float* blr = (const float*)d_in[11];
    const float* Wch = (const float*)d_in[12];
    const float* bch = (const float*)d_in[13];
    const float* Wlh = (const float*)d_in[14];
    const float* blh = (const float*)d_in[15];
    const float* hW  = (const float*)d_in[16];
    const float* hb  = (const float*)d_in[17];
    float* out = (float*)d_out;

    void* p;
    cudaGetSymbolAddress(&p, g_agg_all);
    const float* agg_all = (const float*)p;
    cudaGetSymbolAddress(&p, g_aggh);
    float* aggh = (float*)p;

    static int s_init_done = 0;
    static cudaStream_t s2;
    static cudaEvent_t evFork;
    static cudaEvent_t evT[TT];
    if (!s_init_done) {
        cudaFuncSetAttribute(k_cell, cudaFuncAttributeMaxDynamicSharedMemorySize,
                             SMEM_CELL);
        cudaStreamCreateWithFlags(&s2, cudaStreamNonBlocking);
        cudaEventCreateWithFlags(&evFork, cudaEventDisableTiming);
        for (int t = 0; t < TT; ++t)
            cudaEventCreateWithFlags(&evT[t], cudaEventDisableTiming);
        s_init_done = 1;
    }

    const int THR = 256;
    const float* Wlh_bot = Wlh + 128 * 128;

    // slots 1-3: weight prep + detect; slot 4: ncu PROBE (1-block cell,
    // deterministic; its g_h writes are zeroed by k_init below)
    k_fuse<<<(6528 + 128 * 256 + THR - 1) / THR, THR>>>(Wcz, Wlz, blz, bcz,
                                                        Wcr, Wlr, blr, bcr,
                                                        Wch, Wlh, blh, bch);
    k_fuse2<<<(3 * KTOT * 128 + THR - 1) / THR, THR>>>(Wlh_bot);
    k_detect<<<1, THR>>>(mraw);
    k_cell<<<1, THR_CELL, SMEM_CELL>>>(agg_all, 0, 0, hW, hb, nullptr, nullptr);
    k_convert<<<(NN + THR - 1) / THR, THR>>>(mraw);
    k_init<<<(NN * HH + THR - 1) / THR, THR>>>();

    // fork: t=1..11 aggregation chains on s2; t=0 chain stays on main
    cudaEventRecord(evFork, 0);
    cudaStreamWaitEvent(s2, evFork, 0);

    k_deg_rng<<<(EE + THR - 1) / THR, THR>>>(ei, ea, 0, 1);
    k_dinv_rng<<<(NN + THR - 1) / THR, THR>>>(0, 1);
    k_aggself_rng<<<(NN + THR - 1) / THR, THR>>>(x_seq, 0, 1);
    k_scatter_one<<<(EE + THR - 1) / THR, THR>>>(ei, ea, x_seq, 0);

    k_deg_rng<<<(11 * EE + THR - 1) / THR, THR, 0, s2>>>(ei, ea, 1, 11);
    k_dinv_rng<<<(11 * NN + THR - 1) / THR, THR, 0, s2>>>(1, 11);
    k_aggself_rng<<<(11 * NN + THR - 1) / THR, THR, 0, s2>>>(x_seq, 1, 11);
    for (int t = 1; t < TT; ++t) {
        k_scatter_one<<<(EE + THR - 1) / THR, THR, 0, s2>>>(ei, ea, x_seq, t);
        cudaEventRecord(evT[t], s2);
    }

    dim3 gC((NN + 127) / 128);

    for (int t = 0; t < TT; ++t) {
        if (t > 0) cudaStreamWaitEvent(0, evT[t], 0);
        const float* aggt = agg_all + (size_t)t * NN * FF;
        int flags = (t == 11) ? 2 : 0;
        if (t == 0) flags |= 4;
        k_cell<<<gC, THR_CELL, SMEM_CELL>>>(aggt, t, flags, hW, hb,
                                            nullptr, nullptr);
    }

    const float* agg11 = agg_all + (size_t)11 * NN * FF;
    k_transition<<<(NN * FF + THR - 1) / THR, THR>>>(agg11);

    const int* eiL = ei + (size_t)11 * 2 * EE;

    for (int k = 0; k < HOR; ++k) {
        const float* aggk = (k == 0) ? agg11 : (aggh + (size_t)(k & 1) * NN * FF);
        float* agghN = aggh + (size_t)((k + 1) & 1) * NN * FF;
        if (k > 0) {
            const float* predPrev = out + (size_t)(k - 1) * NN * OUTD;
            k_scatter3<<<(EE + THR - 1) / THR, THR>>>(
                eiL, predPrev, aggh + (size_t)(k & 1) * NN * FF);
        }
        k_cell<<<gC, THR_CELL, SMEM_CELL>>>(aggk, 11, 1, hW, hb,
                                            out + (size_t)k * NN * OUTD, agghN);
    }
}

// round 14
// speedup vs baseline: 1.0831x; 1.0831x over previous
#include <cuda_runtime.h>
#include <cuda_bf16.h>
#include <math.h>

#define NN 50000
#define EE 1600000
#define TT 12
#define FF 16
#define HH 128
#define OUTD 3
#define HOR 6

#define KTOT 144            // 128 (h) + 16 (agg)
#define ASTRIDE 152         // bf16 units per row (304 B) -> conflict-free ldmatrix
#define ROWB (ASTRIDE * 2)  // 304 bytes

// smem layout (bytes)
#define OFF_AHI 0
#define OFF_ALO 38912
#define OFF_BHI 77824
#define OFF_BLO 116736
#define OFF_HS  155648      // hs fp32 [128][129]
#define SMEM_CELL (155648 + 128 * 129 * 4)   // 221696

#define THR_CELL 512

// ---------------- scratch ----------------
__device__ float g_dinv_all[TT * NN];
__device__ float g_agg_all[(size_t)TT * NN * FF];
__device__ float g_aggh[2 * NN * FF];
__device__ float g_nrm11[EE];
__device__ float g_h[NN * HH];
__device__ float g_hw[NN * HH];
__device__ unsigned char g_maskc[TT * NN];
__device__ unsigned char g_meff[TT * NN];
__device__ float g_Bzr_top[16 * 256];
__device__ float g_bzr[256];
__device__ float g_Bzr_bot[128 * 256];
__device__ float g_Bh_top[16 * 128];
__device__ float g_bh[128];
__device__ int g_isbyte;
// bf16 weight splits, [n][ASTRIDE] row-major (k contiguous), per gate {z,r,h}
__device__ __align__(16) unsigned short g_Bsp_hi[3][128 * ASTRIDE];
__device__ __align__(16) unsigned short g_Bsp_lo[3][128 * ASTRIDE];

// ---------------- helpers ----------------
__device__ __forceinline__ unsigned int s2u(const void* p) {
    unsigned int a;
    asm("{ .reg .u64 t; cvta.to.shared.u64 t, %1; cvt.u32.u64 %0, t; }"
        : "=r"(a) : "l"(p));
    return a;
}
__device__ __forceinline__ float bfr(float x) {
    return __bfloat162float(__float2bfloat16_rn(x));
}
__device__ __forceinline__ unsigned int pkbf(float lo, float hi) {  // lo -> low half
    unsigned int r;
    asm("cvt.rn.bf16x2.f32 %0, %1, %2;" : "=r"(r) : "f"(hi), "f"(lo));
    return r;
}
__device__ __forceinline__ void ldm4(unsigned int* r, unsigned int addr) {
    asm volatile("ldmatrix.sync.aligned.m8n8.x4.shared.b16 {%0,%1,%2,%3}, [%4];"
        : "=r"(r[0]), "=r"(r[1]), "=r"(r[2]), "=r"(r[3]) : "r"(addr));
}
__device__ __forceinline__ void mma_bf(float* d, const unsigned int* a,
                                       const unsigned int* b) {
    asm volatile(
        "mma.sync.aligned.m16n8k16.row.col.f32.bf16.bf16.f32 "
        "{%0,%1,%2,%3}, {%4,%5,%6,%7}, {%8,%9}, {%0,%1,%2,%3};"
        : "+f"(d[0]), "+f"(d[1]), "+f"(d[2]), "+f"(d[3])
        : "r"(a[0]), "r"(a[1]), "r"(a[2]), "r"(a[3]), "r"(b[0]), "r"(b[1]));
}
__device__ __forceinline__ float sigmoidf_(float v) {
    return __fdividef(1.0f, 1.0f + __expf(-v));
}
__device__ __forceinline__ float tanhf_(float v) {
    // tanh(v) = 1 - 2/(exp(2v)+1); saturates correctly at +-inf
    float e = __expf(2.0f * v);
    return 1.0f - __fdividef(2.0f, e + 1.0f);
}

// ---------------- mask detection / conversion ----------------
__global__ void k_detect(const unsigned char* raw) {
    __shared__ int cnt;
    if (threadIdx.x == 0) cnt = 0;
    __syncthreads();
    int c = 0;
    for (int i = threadIdx.x; i < 4096; i += blockDim.x) c += (raw[i] != 0);
    atomicAdd(&cnt, c);
    __syncthreads();
    if (threadIdx.x == 0) g_isbyte = (cnt > 2048) ? 1 : 0;
}
__global__ void k_convert(const unsigned char* raw) {
    int n = blockIdx.x * blockDim.x + threadIdx.x;
    if (n >= NN) return;
    int isb = g_isbyte, seen = 0;
#pragma unroll
    for (int t = 0; t < TT; ++t) {
        int m = isb ? (raw[t * NN + n] != 0) : (((const int*)raw)[t * NN + n] != 0);
        g_maskc[t * NN + n] = (unsigned char)m;
        g_meff[t * NN + n] = (unsigned char)(m & seen);
        seen |= m;
    }
}

// ---------------- weight fusion ----------------
__global__ void k_fuse(const float* __restrict__ Wcz, const float* __restrict__ Wlz,
                       const float* __restrict__ blz, const float* __restrict__ bcz,
                       const float* __restrict__ Wcr, const float* __restrict__ Wlr,
                       const float* __restrict__ blr, const float* __restrict__ bcr,
                       const float* __restrict__ Wch, const float* __restrict__ Wlh,
                       const float* __restrict__ blh, const float* __restrict__ bch) {
    int i = blockIdx.x * blockDim.x + threadIdx.x;
    if (i < 16 * 256) {
        int k = i / 256, c = i % 256, cc = c & 127;
        const float* A = (c < 128) ? Wcz : Wcr;
        const float* B = (c < 128) ? Wlz : Wlr;
        float s = 0.f;
        for (int j = 0; j < 128; ++j) s += A[k * 128 + j] * B[j * 128 + cc];
        g_Bzr_top[i] = s;
    } else if (i < 4096 + 2048) {
        int r = i - 4096; int k = r / 128, c = r % 128;
        float s = 0.f;
        for (int j = 0; j < 128; ++j) s += Wch[k * 128 + j] * Wlh[j * 128 + c];
        g_Bh_top[r] = s;
    } else if (i < 6144 + 256) {
        int c = i - 6144; int cc = c & 127;
        const float* bc = (c < 128) ? bcz : bcr;
        const float* B  = (c < 128) ? Wlz : Wlr;
        const float* bl = (c < 128) ? blz : blr;
        float s = bl[cc];
        for (int j = 0; j < 128; ++j) s += bc[j] * B[j * 128 + cc];
        g_bzr[c] = s;
    } else if (i < 6400 + 128) {
        int c = i - 6400;
        float s = blh[c];
        for (int j = 0; j < 128; ++j) s += bch[j] * Wlh[j * 128 + c];
        g_bh[c] = s;
    } else if (i < 6528 + 128 * 256) {
        int r = i - 6528; int k = r / 256, c = r % 256;
        g_Bzr_bot[r] = (c < 128) ? Wlz[(128 + k) * 128 + c]
                                 : Wlr[(128 + k) * 128 + (c - 128)];
    }
}

// bf16 hi/lo splits: B[n][k] = W[k][n]; k 0..127 = bottom, 128..143 = top
__global__ void k_fuse2(const float* __restrict__ Wlh_bot) {
    int i = blockIdx.x * blockDim.x + threadIdx.x;
    if (i >= 3 * KTOT * 128) return;
    int g = i / (KTOT * 128), r = i - g * (KTOT * 128);
    int k = r / 128, n = r - k * 128;
    float w;
    if (k < 128) {
        if (g == 0)      w = g_Bzr_bot[k * 256 + n];
        else if (g == 1) w = g_Bzr_bot[k * 256 + 128 + n];
        else             w = Wlh_bot[k * 128 + n];
    } else {
        int kt = k - 128;
        if (g == 0)      w = g_Bzr_top[kt * 256 + n];
        else if (g == 1) w = g_Bzr_top[kt * 256 + 128 + n];
        else             w = g_Bh_top[kt * 128 + n];
    }
    float wh = bfr(w);
    g_Bsp_hi[g][n * ASTRIDE + k] = __bfloat16_as_ushort(__float2bfloat16_rn(wh));
    g_Bsp_lo[g][n * ASTRIDE + k] = __bfloat16_as_ushort(__float2bfloat16_rn(w - wh));
}

__global__ void k_init() {
    int i = blockIdx.x * blockDim.x + threadIdx.x;
    if (i < NN * HH) g_h[i] = 0.f;
    if (i < TT * NN) g_dinv_all[i] = 0.f;
}

// ---------------- degree / aggregation (batched, R12 scheduling) ----------------
__global__ void k_deg_all(const int* __restrict__ ei, const float* __restrict__ ea) {
    int e = blockIdx.x * blockDim.x + threadIdx.x;
    if (e >= TT * EE) return;
    int t = e / EE, le = e - t * EE;
    int dst = ei[(size_t)t * 2 * EE + EE + le];
    atomicAdd(&g_dinv_all[t * NN + dst], ea[(size_t)t * EE + le]);
}
__global__ void k_dinv_fin() {
    int i = blockIdx.x * blockDim.x + threadIdx.x;
    if (i < TT * NN) g_dinv_all[i] = rsqrtf(g_dinv_all[i] + 1.0f);
}
__global__ void k_aggself_all(const float* __restrict__ x_seq) {
    int i = blockIdx.x * blockDim.x + threadIdx.x;
    if (i >= TT * NN) return;
    int t = i / NN, n = i - t * NN;
    float di = g_dinv_all[i];
    float s = di * di;
    const float4* xp = (const float4*)(x_seq + (size_t)t * NN * FF + (size_t)n * FF);
    float4* op = (float4*)(g_agg_all + (size_t)t * NN * FF + (size_t)n * FF);
    float4 a = xp[0], b = xp[1], c = xp[2], d = xp[3];
    op[0] = make_float4(s * a.x, s * a.y, s * a.z, s * a.w);
    op[1] = make_float4(s * b.x, s * b.y, s * b.z, s * b.w);
    op[2] = make_float4(s * c.x, s * c.y, s * c.z, s * c.w);
    op[3] = make_float4(s * d.x, s * d.y, s * d.z, s * d.w);
}
#define REDV4(p, a, b, c, d)                                              \
    asm volatile("red.global.add.v4.f32 [%0], {%1,%2,%3,%4};"             \
                 :: "l"(p), "f"(a), "f"(b), "f"(c), "f"(d) : "memory")
#define REDV2(p, a, b)                                                    \
    asm volatile("red.global.add.v2.f32 [%0], {%1,%2};"                   \
                 :: "l"(p), "f"(a), "f"(b) : "memory")
#define RED1(p, a)                                                        \
    asm volatile("red.global.add.f32 [%0], %1;"                           \
                 :: "l"(p), "f"(a) : "memory")
__global__ void k_scatter_one(const int* __restrict__ ei, const float* __restrict__ ea,
                              const float* __restrict__ x_seq, int t) {
    int le = blockIdx.x * blockDim.x + threadIdx.x;
    if (le >= EE) return;
    const int* eit = ei + (size_t)t * 2 * EE;
    int s = eit[le], d = eit[EE + le];
    const float* dinv = g_dinv_all + t * NN;
    float nrm = dinv[s] * ea[(size_t)t * EE + le] * dinv[d];
    if (t == 11) g_nrm11[le] = nrm;
    const float4* xp = (const float4*)(x_seq + (size_t)t * NN * FF + (size_t)s * FF);
    float4 a = xp[0], b = xp[1], c = xp[2], dd = xp[3];
    float* o = g_agg_all + (size_t)t * NN * FF + (size_t)d * FF;
    REDV4(o + 0,  nrm * a.x,  nrm * a.y,  nrm * a.z,  nrm * a.w);
    REDV4(o + 4,  nrm * b.x,  nrm * b.y,  nrm * b.z,  nrm * b.w);
    REDV4(o + 8,  nrm * c.x,  nrm * c.y,  nrm * c.z,  nrm * c.w);
    REDV4(o + 12, nrm * dd.x, nrm * dd.y, nrm * dd.z, nrm * dd.w);
}

// ---------------- fused TGCN cell: mma.sync bf16 split GEMMs ----------------
// flags: bit0 = horizon, bit1 = write g_hw = mk ? hn : 0 (t==11), bit2 = h_eff==0
__global__ __launch_bounds__(THR_CELL, 1)
void k_cell(const float* __restrict__ agg, int t, int flags,
            const float* __restrict__ headW, const float* __restrict__ headb,
            float* __restrict__ outk, float* __restrict__ agghN) {
    extern __shared__ __align__(16) char smc[];
    char*  Ahi = smc + OFF_AHI;
    char*  Alo = smc + OFF_ALO;
    char*  Bhi = smc + OFF_BHI;
    char*  Blo = smc + OFF_BLO;
    float* hs  = (float*)(smc + OFF_HS);
    unsigned int sbase = s2u(smc);

    const int tid = threadIdx.x;
    const int nblk = blockIdx.x * 128;
    const bool horizon = (flags & 1) != 0;
    const bool wrHw = (flags & 2) != 0;
    const bool hz = (flags & 4) != 0;
    const float* hsrc = horizon ? g_hw : g_h;
    const unsigned char* me = g_meff + (size_t)t * NN;
    const unsigned char* mk = g_maskc + (size_t)t * NN;

    const int w = tid >> 5, l = tid & 31;
    const int m0 = (w & 3) * 32, n0 = (w >> 2) * 32;
    const int fg = l >> 2, fc = l & 3;

    // ---- staging: A (h split + agg split), hs fp32, B gate-z ----
    {
        int row = tid >> 2, q = tid & 3;
        int nA = nblk + row;
        bool rowValid = nA < NN;
        bool rowOn = rowValid && (horizon || (me[nA] != 0));
        char* arow_h = Ahi + row * ROWB;
        char* arow_l = Alo + row * ROWB;
#pragma unroll
        for (int g8 = 0; g8 < 8; ++g8) {
            int k0 = q * 32 + g8 * 4;
            float4 v = make_float4(0.f, 0.f, 0.f, 0.f);
            if (rowOn) v = *(const float4*)(hsrc + (size_t)nA * HH + k0);
            hs[row * 129 + k0 + 0] = v.x;
            hs[row * 129 + k0 + 1] = v.y;
            hs[row * 129 + k0 + 2] = v.z;
            hs[row * 129 + k0 + 3] = v.w;
            float xh = bfr(v.x), yh = bfr(v.y), zh = bfr(v.z), wh = bfr(v.w);
            *(unsigned int*)(arow_h + k0 * 2)     = pkbf(xh, yh);
            *(unsigned int*)(arow_h + k0 * 2 + 4) = pkbf(zh, wh);
            *(unsigned int*)(arow_l + k0 * 2)     = pkbf(v.x - xh, v.y - yh);
            *(unsigned int*)(arow_l + k0 * 2 + 4) = pkbf(v.z - zh, v.w - wh);
        }
        {
            float4 v = make_float4(0.f, 0.f, 0.f, 0.f);
            if (rowValid) v = *(const float4*)(agg + (size_t)nA * 16 + 4 * q);
            int kb = (128 + q * 4) * 2;
            float xh = bfr(v.x), yh = bfr(v.y), zh = bfr(v.z), wh = bfr(v.w);
            *(unsigned int*)(arow_h + kb)     = pkbf(xh, yh);
            *(unsigned int*)(arow_h + kb + 4) = pkbf(zh, wh);
            *(unsigned int*)(arow_l + kb)     = pkbf(v.x - xh, v.y - yh);
            *(unsigned int*)(arow_l + kb + 4) = pkbf(v.z - zh, v.w - wh);
        }
        const float4* sh = (const float4*)g_Bsp_hi[0];
        const float4* sl = (const float4*)g_Bsp_lo[0];
        float4* dh = (float4*)Bhi;
        float4* dl = (float4*)Blo;
        for (int i = tid; i < 128 * ASTRIDE / 8; i += THR_CELL) {
            dh[i] = sh[i]; dl[i] = sl[i];
        }
    }
    __syncthreads();

    unsigned int aHiAd = sbase + OFF_AHI + (m0 + (l & 15)) * ROWB + (l >> 4) * 16;
    unsigned int aLoAd = aHiAd + (OFF_ALO - OFF_AHI);
    unsigned int bHiAd = sbase + OFF_BHI +
                         (n0 + (l >> 4) * 8 + (l & 7)) * ROWB + ((l >> 3) & 1) * 16;
    unsigned int bLoAd = bHiAd + (OFF_BLO - OFF_BHI);
    const int kt0 = hz ? 8 : 0;

    float dd[32];
    float zreg[32];

#define GATE_MMA()                                                          \
    _Pragma("unroll") for (int j = 0; j < 32; ++j) dd[j] = 0.f;             \
    for (int kt = kt0; kt < 9; ++kt) {                                      \
        unsigned int ah[2][4], al[2][4], bh[2][4], bl[2][4];                \
        ldm4(ah[0], aHiAd + kt * 32);                                       \
        ldm4(ah[1], aHiAd + kt * 32 + 16 * ROWB);                           \
        ldm4(al[0], aLoAd + kt * 32);                                       \
        ldm4(al[1], aLoAd + kt * 32 + 16 * ROWB);                           \
        ldm4(bh[0], bHiAd + kt * 32);                                       \
        ldm4(bh[1], bHiAd + kt * 32 + 16 * ROWB);                           \
        ldm4(bl[0], bLoAd + kt * 32);                                       \
        ldm4(bl[1], bLoAd + kt * 32 + 16 * ROWB);                           \
        _Pragma("unroll") for (int am = 0; am < 2; ++am)                    \
        _Pragma("unroll") for (int bn = 0; bn < 4; ++bn) {                  \
            float* dp = dd + (am * 4 + bn) * 4;                             \
            const unsigned int* bhp = &bh[bn >> 1][(bn & 1) * 2];           \
            const unsigned int* blp = &bl[bn >> 1][(bn & 1) * 2];           \
            mma_bf(dp, ah[am], bhp);                                        \
            mma_bf(dp, ah[am], blp);                                        \
            mma_bf(dp, al[am], bhp);                                        \
        }                                                                   \
    }

    // ================= gate Z =================
    GATE_MMA();
#pragma unroll
    for (int am = 0; am < 2; ++am)
#pragma unroll
    for (int bn = 0; bn < 4; ++bn)
#pragma unroll
    for (int e = 0; e < 4; ++e) {
        int idx = (am * 4 + bn) * 4 + e;
        int col = n0 + 8 * bn + 2 * fc + (e & 1);
        zreg[idx] = sigmoidf_(dd[idx] + g_bzr[col]);
    }
    __syncthreads();
    {
        const float4* sh = (const float4*)g_Bsp_hi[1];
        const float4* sl = (const float4*)g_Bsp_lo[1];
        float4* dh = (float4*)Bhi;
        float4* dl = (float4*)Blo;
        for (int i = tid; i < 128 * ASTRIDE / 8; i += THR_CELL) {
            dh[i] = sh[i]; dl[i] = sl[i];
        }
    }
    __syncthreads();

    // ================= gate R =================
    GATE_MMA();
    __syncthreads();   // all warps done reading A before hr overwrites it
#pragma unroll
    for (int am = 0; am < 2; ++am)
#pragma unroll
    for (int bn = 0; bn < 4; ++bn)
#pragma unroll
    for (int eh = 0; eh < 2; ++eh) {
        int idx = (am * 4 + bn) * 4 + eh * 2;
        int row = m0 + 16 * am + fg + eh * 8;
        int cb = n0 + 8 * bn + 2 * fc;
        float r0 = sigmoidf_(dd[idx]     + g_bzr[128 + cb]);
        float r1 = sigmoidf_(dd[idx + 1] + g_bzr[128 + cb + 1]);
        if (!hz) {
            float p0 = hs[row * 129 + cb] * r0;
            float p1 = hs[row * 129 + cb + 1] * r1;
            float p0h = bfr(p0), p1h = bfr(p1);
            *(unsigned int*)(Ahi + row * ROWB + cb * 2) = pkbf(p0h, p1h);
            *(unsigned int*)(Alo + row * ROWB + cb * 2) = pkbf(p0 - p0h, p1 - p1h);
        }
    }
    __syncthreads();
    {
        const float4* sh = (const float4*)g_Bsp_hi[2];
        const float4* sl = (const float4*)g_Bsp_lo[2];
        float4* dh = (float4*)Bhi;
        float4* dl = (float4*)Blo;
        for (int i = tid; i < 128 * ASTRIDE / 8; i += THR_CELL) {
            dh[i] = sh[i]; dl[i] = sl[i];
        }
    }
    __syncthreads();

    // ================= gate H + combine =================
    GATE_MMA();
#pragma unroll
    for (int am = 0; am < 2; ++am)
#pragma unroll
    for (int bn = 0; bn < 4; ++bn)
#pragma unroll
    for (int e = 0; e < 4; ++e) {
        int idx = (am * 4 + bn) * 4 + e;
        int row = m0 + 16 * am + fg + (e >> 1) * 8;
        int col = n0 + 8 * bn + 2 * fc + (e & 1);
        float ht = tanhf_(dd[idx] + g_bh[col]);
        float z = zreg[idx];
        float h0 = hs[row * 129 + col];
        hs[row * 129 + col] = z * h0 + (1.f - z) * ht;
    }
    __syncthreads();

    if (horizon && tid < 96) {
        float4 wv = *(const float4*)(headW + tid * 4);
        ((float*)Bhi)[tid * 4 + 0] = wv.x; ((float*)Bhi)[tid * 4 + 1] = wv.y;
        ((float*)Bhi)[tid * 4 + 2] = wv.z; ((float*)Bhi)[tid * 4 + 3] = wv.w;
    }

    // ---- coalesced masked writeback ----
    {
        int row = tid >> 2, cg = (tid & 3) * 32;
        int n = nblk + row;
        if (n < NN) {
            bool wr = horizon ? true : (mk[n] != 0);
#pragma unroll
            for (int i4 = 0; i4 < 8; ++i4) {
                float4 v;
                v.x = hs[row * 129 + cg + 4 * i4 + 0];
                v.y = hs[row * 129 + cg + 4 * i4 + 1];
                v.z = hs[row * 129 + cg + 4 * i4 + 2];
                v.w = hs[row * 129 + cg + 4 * i4 + 3];
                if (horizon) {
                    *(float4*)(g_hw + (size_t)n * HH + cg + 4 * i4) = v;
                } else {
                    if (wr) *(float4*)(g_h + (size_t)n * HH + cg + 4 * i4) = v;
                    if (wrHw) {
                        float4 vz = wr ? v : make_float4(0.f, 0.f, 0.f, 0.f);
                        *(float4*)(g_hw + (size_t)n * HH + cg + 4 * i4) = vz;
                    }
                }
            }
        }
    }

    // ---- fused head prediction (horizon): 4 threads per node + shfl reduce ----
    if (horizon) {
        __syncthreads();
        int row = tid >> 2, pp = tid & 3;
        int n = nblk + row;
        const float* hwv = (const float*)Bhi;
        float p0 = 0.f, p1 = 0.f, p2 = 0.f;
        int c0 = pp * 32;
#pragma unroll 8
        for (int c = c0; c < c0 + 32; ++c) {
            float hv = hs[row * 129 + c];
            p0 += hv * hwv[c * 3 + 0];
            p1 += hv * hwv[c * 3 + 1];
            p2 += hv * hwv[c * 3 + 2];
        }
#pragma unroll
        for (int o = 2; o >= 1; o >>= 1) {
            p0 += __shfl_down_sync(0xFFFFFFFFu, p0, o, 4);
            p1 += __shfl_down_sync(0xFFFFFFFFu, p1, o, 4);
            p2 += __shfl_down_sync(0xFFFFFFFFu, p2, o, 4);
        }
        if (pp == 0 && n < NN) {
            p0 += headb[0]; p1 += headb[1]; p2 += headb[2];
            outk[n * 3 + 0] = p0;
            outk[n * 3 + 1] = p1;
            outk[n * 3 + 2] = p2;
            float di = g_dinv_all[11 * NN + n];
            float s = di * di;
            agghN[n * FF + 0] = s * p0;
            agghN[n * FF + 1] = s * p1;
            agghN[n * FF + 2] = s * p2;
        }
    }
}

// ---------------- transition / horizon helpers ----------------
__global__ void k_transition(const float* __restrict__ agg11) {
    int i = blockIdx.x * blockDim.x + threadIdx.x;
    if (i >= NN * FF) return;
    float v = agg11[i];
    g_aggh[i] = v;
    g_aggh[NN * FF + i] = v;
}
__global__ void k_scatter3(const int* __restrict__ ei11,
                           const float* __restrict__ pred,
                           float* __restrict__ target) {
    int e = blockIdx.x * blockDim.x + threadIdx.x;
    if (e >= EE) return;
    int s = ei11[e], d = ei11[EE + e];
    float nrm = g_nrm11[e];
    float p0 = pred[s * 3 + 0], p1 = pred[s * 3 + 1], p2 = pred[s * 3 + 2];
    float* o = target + (size_t)d * FF;
    REDV2(o, nrm * p0, nrm * p1);
    RED1(o + 2, nrm * p2);
}

// ---------------- launch ----------------
extern "C" void kernel_launch(void* const* d_in, const int* in_sizes, int n_in,
                              void* d_out, int out_size) {
    const float* x_seq = (const float*)d_in[0];
    const int*   ei    = (const int*)d_in[1];
    const float* ea    = (const float*)d_in[2];
    const unsigned char* mraw = (const unsigned char*)d_in[3];
    const float* Wcz = (const float*)d_in[4];
    const float* bcz = (const float*)d_in[5];
    const float* Wlz = (const float*)d_in[6];
    const float* blz = (const float*)d_in[7];
    const float* Wcr = (const float*)d_in[8];
    const float* bcr = (const float*)d_in[9];
    const float* Wlr = (const float*)d_in[10];
    const float* blr = (const float*)d_in[11];
    const float* Wch = (const float*)d_in[12];
    const float* bch = (const float*)d_in[13];
    const float* Wlh = (const float*)d_in[14];
    const float* blh = (const float*)d_in[15];
    const float* hW  = (const float*)d_in[16];
    const float* hb  = (const float*)d_in[17];
    float* out = (float*)d_out;

    void* p;
    cudaGetSymbolAddress(&p, g_agg_all);
    const float* agg_all = (const float*)p;
    cudaGetSymbolAddress(&p, g_aggh);
    float* aggh = (float*)p;

    static int s_init_done = 0;
    static cudaStream_t s2;
    static cudaEvent_t evFork;
    static cudaEvent_t evT[TT];
    if (!s_init_done) {
        cudaFuncSetAttribute(k_cell, cudaFuncAttributeMaxDynamicSharedMemorySize,
                             SMEM_CELL);
        cudaStreamCreateWithFlags(&s2, cudaStreamNonBlocking);
        cudaEventCreateWithFlags(&evFork, cudaEventDisableTiming);
        for (int t = 0; t < TT; ++t)
            cudaEventCreateWithFlags(&evT[t], cudaEventDisableTiming);
        s_init_done = 1;
    }

    const int THR = 256;
    const float* Wlh_bot = Wlh + 128 * 128;

    // ---- prologue (main stream), R12 scheduling ----
    k_detect<<<1, THR>>>(mraw);
    k_convert<<<(NN + THR - 1) / THR, THR>>>(mraw);
    k_fuse<<<(6528 + 128 * 256 + THR - 1) / THR, THR>>>(Wcz, Wlz, blz, bcz,
                                                        Wcr, Wlr, blr, bcr,
                                                        Wch, Wlh, blh, bch);
    k_fuse2<<<(3 * KTOT * 128 + THR - 1) / THR, THR>>>(Wlh_bot);
    k_init<<<(NN * HH + THR - 1) / THR, THR>>>();
    k_deg_all<<<(TT * EE + THR - 1) / THR, THR>>>(ei, ea);
    k_dinv_fin<<<(TT * NN + THR - 1) / THR, THR>>>();
    k_aggself_all<<<(TT * NN + THR - 1) / THR, THR>>>(x_seq);
    k_scatter_one<<<(EE + THR - 1) / THR, THR>>>(ei, ea, x_seq, 0);

    // ---- fork: per-t scatters on s2, cells on main ----
    cudaEventRecord(evFork, 0);
    cudaStreamWaitEvent(s2, evFork, 0);
    for (int t = 1; t < TT; ++t) {
        k_scatter_one<<<(EE + THR - 1) / THR, THR, 0, s2>>>(ei, ea, x_seq, t);
        cudaEventRecord(evT[t], s2);
    }

    dim3 gC((NN + 127) / 128);

    for (int t = 0; t < TT; ++t) {
        if (t > 0) cudaStreamWaitEvent(0, evT[t], 0);
        const float* aggt = agg_all + (size_t)t * NN * FF;
        int flags = (t == 11) ? 2 : 0;
        if (t == 0) flags |= 4;
        k_cell<<<gC, THR_CELL, SMEM_CELL>>>(aggt, t, flags, hW, hb,
                                            nullptr, nullptr);
    }

    const float* agg11 = agg_all + (size_t)11 * NN * FF;
    k_transition<<<(NN * FF + THR - 1) / THR, THR>>>(agg11);

    const int* eiL = ei + (size_t)11 * 2 * EE;

    for (int k = 0; k < HOR; ++k) {
        const float* aggk = (k == 0) ? agg11 : (aggh + (size_t)(k & 1) * NN * FF);
        float* agghN = aggh + (size_t)((k + 1) & 1) * NN * FF;
        if (k > 0) {
            const float* predPrev = out + (size_t)(k - 1) * NN * OUTD;
            k_scatter3<<<(EE + THR - 1) / THR, THR>>>(
                eiL, predPrev, aggh + (size_t)(k & 1) * NN * FF);
        }
        k_cell<<<gC, THR_CELL, SMEM_CELL>>>(aggk, 11, 1, hW, hb,
                                            out + (size_t)k * NN * OUTD, agghN);
    }
}

// round 15
// speedup vs baseline: 1.1667x; 1.0772x over previous
#include <cuda_runtime.h>
#include <cuda_bf16.h>
#include <math.h>

#define NN 50000
#define EE 1600000
#define TT 12
#define FF 16
#define HH 128
#define OUTD 3
#define HOR 6

#define KTOT 144            // 128 (h) + 16 (agg)
#define ASTRIDE 152         // bf16 units per row (304 B) -> conflict-free ldmatrix
#define ROWB (ASTRIDE * 2)  // 304 bytes

// smem layout (bytes)
#define OFF_AHI 0
#define OFF_ALO 38912
#define OFF_BHI 77824
#define OFF_BLO 116736
#define OFF_HS  155648      // hs fp32 [128][129]
#define SMEM_CELL (155648 + 128 * 129 * 4)   // 221696

#define THR_CELL 512

// ---------------- scratch ----------------
__device__ float g_dinv_all[TT * NN];
__device__ float g_agg_all[(size_t)TT * NN * FF];
__device__ float g_aggh[2 * NN * FF];
__device__ float g_nrm11[EE];
__device__ float g_h[NN * HH];
__device__ float g_hw[NN * HH];
__device__ unsigned char g_maskc[TT * NN];
__device__ unsigned char g_meff[TT * NN];
__device__ float g_Bzr_top[16 * 256];
__device__ float g_bzr[256];
__device__ float g_Bzr_bot[128 * 256];
__device__ float g_Bh_top[16 * 128];
__device__ float g_bh[128];
__device__ int g_isbyte;
// bf16 weight splits, [n][ASTRIDE] row-major (k contiguous), per gate {z,r,h}
__device__ __align__(16) unsigned short g_Bsp_hi[3][128 * ASTRIDE];
__device__ __align__(16) unsigned short g_Bsp_lo[3][128 * ASTRIDE];

// ---------------- helpers ----------------
__device__ __forceinline__ unsigned int s2u(const void* p) {
    unsigned int a;
    asm("{ .reg .u64 t; cvta.to.shared.u64 t, %1; cvt.u32.u64 %0, t; }"
        : "=r"(a) : "l"(p));
    return a;
}
__device__ __forceinline__ float bfr(float x) {
    return __bfloat162float(__float2bfloat16_rn(x));
}
__device__ __forceinline__ unsigned int pkbf(float lo, float hi) {  // lo -> low half
    unsigned int r;
    asm("cvt.rn.bf16x2.f32 %0, %1, %2;" : "=r"(r) : "f"(hi), "f"(lo));
    return r;
}
__device__ __forceinline__ void ldm4(unsigned int* r, unsigned int addr) {
    asm volatile("ldmatrix.sync.aligned.m8n8.x4.shared.b16 {%0,%1,%2,%3}, [%4];"
        : "=r"(r[0]), "=r"(r[1]), "=r"(r[2]), "=r"(r[3]) : "r"(addr));
}
__device__ __forceinline__ void mma_bf(float* d, const unsigned int* a,
                                       const unsigned int* b) {
    asm volatile(
        "mma.sync.aligned.m16n8k16.row.col.f32.bf16.bf16.f32 "
        "{%0,%1,%2,%3}, {%4,%5,%6,%7}, {%8,%9}, {%0,%1,%2,%3};"
        : "+f"(d[0]), "+f"(d[1]), "+f"(d[2]), "+f"(d[3])
        : "r"(a[0]), "r"(a[1]), "r"(a[2]), "r"(a[3]), "r"(b[0]), "r"(b[1]));
}
__device__ __forceinline__ float sigmoidf_(float v) {
    return __fdividef(1.0f, 1.0f + __expf(-v));
}
__device__ __forceinline__ float tanhf_(float v) {
    float e = __expf(2.0f * v);
    return 1.0f - __fdividef(2.0f, e + 1.0f);
}
#define CPA16(saddr, gptr) \
    asm volatile("cp.async.cg.shared.global [%0], [%1], 16;" \
                 :: "r"(saddr), "l"(gptr) : "memory")
#define CPA_COMMIT() asm volatile("cp.async.commit_group;" ::: "memory")
#define CPA_WAIT()   asm volatile("cp.async.wait_group 0;" ::: "memory")

// stage next gate's B splits via cp.async (no register round-trip)
__device__ __forceinline__ void stageB_async(unsigned int sbase, int gate, int tid) {
    const char* sh = (const char*)g_Bsp_hi[gate];
    const char* sl = (const char*)g_Bsp_lo[gate];
    unsigned int dh = sbase + OFF_BHI;
    unsigned int dl = sbase + OFF_BLO;
    for (int i = tid; i < 128 * ASTRIDE / 8; i += THR_CELL) {
        CPA16(dh + i * 16, sh + i * 16);
        CPA16(dl + i * 16, sl + i * 16);
    }
    CPA_COMMIT();
}

// ---------------- mask detection / conversion ----------------
__global__ void k_detect(const unsigned char* raw) {
    __shared__ int cnt;
    if (threadIdx.x == 0) cnt = 0;
    __syncthreads();
    int c = 0;
    for (int i = threadIdx.x; i < 4096; i += blockDim.x) c += (raw[i] != 0);
    atomicAdd(&cnt, c);
    __syncthreads();
    if (threadIdx.x == 0) g_isbyte = (cnt > 2048) ? 1 : 0;
}
__global__ void k_convert(const unsigned char* raw) {
    int n = blockIdx.x * blockDim.x + threadIdx.x;
    if (n >= NN) return;
    int isb = g_isbyte, seen = 0;
#pragma unroll
    for (int t = 0; t < TT; ++t) {
        int m = isb ? (raw[t * NN + n] != 0) : (((const int*)raw)[t * NN + n] != 0);
        g_maskc[t * NN + n] = (unsigned char)m;
        g_meff[t * NN + n] = (unsigned char)(m & seen);
        seen |= m;
    }
}

// ---------------- weight fusion ----------------
__global__ void k_fuse(const float* __restrict__ Wcz, const float* __restrict__ Wlz,
                       const float* __restrict__ blz, const float* __restrict__ bcz,
                       const float* __restrict__ Wcr, const float* __restrict__ Wlr,
                       const float* __restrict__ blr, const float* __restrict__ bcr,
                       const float* __restrict__ Wch, const float* __restrict__ Wlh,
                       const float* __restrict__ blh, const float* __restrict__ bch) {
    int i = blockIdx.x * blockDim.x + threadIdx.x;
    if (i < 16 * 256) {
        int k = i / 256, c = i % 256, cc = c & 127;
        const float* A = (c < 128) ? Wcz : Wcr;
        const float* B = (c < 128) ? Wlz : Wlr;
        float s = 0.f;
        for (int j = 0; j < 128; ++j) s += A[k * 128 + j] * B[j * 128 + cc];
        g_Bzr_top[i] = s;
    } else if (i < 4096 + 2048) {
        int r = i - 4096; int k = r / 128, c = r % 128;
        float s = 0.f;
        for (int j = 0; j < 128; ++j) s += Wch[k * 128 + j] * Wlh[j * 128 + c];
        g_Bh_top[r] = s;
    } else if (i < 6144 + 256) {
        int c = i - 6144; int cc = c & 127;
        const float* bc = (c < 128) ? bcz : bcr;
        const float* B  = (c < 128) ? Wlz : Wlr;
        const float* bl = (c < 128) ? blz : blr;
        float s = bl[cc];
        for (int j = 0; j < 128; ++j) s += bc[j] * B[j * 128 + cc];
        g_bzr[c] = s;
    } else if (i < 6400 + 128) {
        int c = i - 6400;
        float s = blh[c];
        for (int j = 0; j < 128; ++j) s += bch[j] * Wlh[j * 128 + c];
        g_bh[c] = s;
    } else if (i < 6528 + 128 * 256) {
        int r = i - 6528; int k = r / 256, c = r % 256;
        g_Bzr_bot[r] = (c < 128) ? Wlz[(128 + k) * 128 + c]
                                 : Wlr[(128 + k) * 128 + (c - 128)];
    }
}

__global__ void k_fuse2(const float* __restrict__ Wlh_bot) {
    int i = blockIdx.x * blockDim.x + threadIdx.x;
    if (i >= 3 * KTOT * 128) return;
    int g = i / (KTOT * 128), r = i - g * (KTOT * 128);
    int k = r / 128, n = r - k * 128;
    float w;
    if (k < 128) {
        if (g == 0)      w = g_Bzr_bot[k * 256 + n];
        else if (g == 1) w = g_Bzr_bot[k * 256 + 128 + n];
        else             w = Wlh_bot[k * 128 + n];
    } else {
        int kt = k - 128;
        if (g == 0)      w = g_Bzr_top[kt * 256 + n];
        else if (g == 1) w = g_Bzr_top[kt * 256 + 128 + n];
        else             w = g_Bh_top[kt * 128 + n];
    }
    float wh = bfr(w);
    g_Bsp_hi[g][n * ASTRIDE + k] = __bfloat16_as_ushort(__float2bfloat16_rn(wh));
    g_Bsp_lo[g][n * ASTRIDE + k] = __bfloat16_as_ushort(__float2bfloat16_rn(w - wh));
}

__global__ void k_init() {
    int i = blockIdx.x * blockDim.x + threadIdx.x;
    if (i < NN * HH) g_h[i] = 0.f;
    if (i < TT * NN) g_dinv_all[i] = 0.f;
}

// ---------------- degree / aggregation (t-ranged) ----------------
__global__ void k_deg_rng(const int* __restrict__ ei, const float* __restrict__ ea,
                          int t0, int nt) {
    int e = blockIdx.x * blockDim.x + threadIdx.x;
    if (e >= nt * EE) return;
    int t = t0 + e / EE, le = e % EE;
    int dst = ei[(size_t)t * 2 * EE + EE + le];
    atomicAdd(&g_dinv_all[t * NN + dst], ea[(size_t)t * EE + le]);
}
__global__ void k_dinv_rng(int t0, int nt) {
    int i = blockIdx.x * blockDim.x + threadIdx.x;
    if (i >= nt * NN) return;
    int idx = t0 * NN + i;
    g_dinv_all[idx] = rsqrtf(g_dinv_all[idx] + 1.0f);
}
__global__ void k_aggself_rng(const float* __restrict__ x_seq, int t0, int nt) {
    int i = blockIdx.x * blockDim.x + threadIdx.x;
    if (i >= nt * NN) return;
    int t = t0 + i / NN, n = i % NN;
    float di = g_dinv_all[t * NN + n];
    float s = di * di;
    const float4* xp = (const float4*)(x_seq + (size_t)t * NN * FF + (size_t)n * FF);
    float4* op = (float4*)(g_agg_all + (size_t)t * NN * FF + (size_t)n * FF);
    float4 a = xp[0], b = xp[1], c = xp[2], d = xp[3];
    op[0] = make_float4(s * a.x, s * a.y, s * a.z, s * a.w);
    op[1] = make_float4(s * b.x, s * b.y, s * b.z, s * b.w);
    op[2] = make_float4(s * c.x, s * c.y, s * c.z, s * c.w);
    op[3] = make_float4(s * d.x, s * d.y, s * d.z, s * d.w);
}
#define REDV4(p, a, b, c, d)                                              \
    asm volatile("red.global.add.v4.f32 [%0], {%1,%2,%3,%4};"             \
                 :: "l"(p), "f"(a), "f"(b), "f"(c), "f"(d) : "memory")
#define REDV2(p, a, b)                                                    \
    asm volatile("red.global.add.v2.f32 [%0], {%1,%2};"                   \
                 :: "l"(p), "f"(a), "f"(b) : "memory")
#define RED1(p, a)                                                        \
    asm volatile("red.global.add.f32 [%0], %1;"                           \
                 :: "l"(p), "f"(a) : "memory")
__global__ void k_scatter_one(const int* __restrict__ ei, const float* __restrict__ ea,
                              const float* __restrict__ x_seq, int t) {
    int le = blockIdx.x * blockDim.x + threadIdx.x;
    if (le >= EE) return;
    const int* eit = ei + (size_t)t * 2 * EE;
    int s = eit[le], d = eit[EE + le];
    const float* dinv = g_dinv_all + t * NN;
    float nrm = dinv[s] * ea[(size_t)t * EE + le] * dinv[d];
    if (t == 11) g_nrm11[le] = nrm;
    const float4* xp = (const float4*)(x_seq + (size_t)t * NN * FF + (size_t)s * FF);
    float4 a = xp[0], b = xp[1], c = xp[2], dd = xp[3];
    float* o = g_agg_all + (size_t)t * NN * FF + (size_t)d * FF;
    REDV4(o + 0,  nrm * a.x,  nrm * a.y,  nrm * a.z,  nrm * a.w);
    REDV4(o + 4,  nrm * b.x,  nrm * b.y,  nrm * b.z,  nrm * b.w);
    REDV4(o + 8,  nrm * c.x,  nrm * c.y,  nrm * c.z,  nrm * c.w);
    REDV4(o + 12, nrm * dd.x, nrm * dd.y, nrm * dd.z, nrm * dd.w);
}

// ---------------- fused TGCN cell: mma.sync bf16 split GEMMs ----------------
// flags: bit0 = horizon, bit1 = write g_hw = mk ? hn : 0 (t==11), bit2 = h_eff==0
__global__ __launch_bounds__(THR_CELL, 1)
void k_cell(const float* __restrict__ agg, int t, int flags,
            const float* __restrict__ headW, const float* __restrict__ headb,
            float* __restrict__ outk, float* __restrict__ agghN) {
    extern __shared__ __align__(16) char smc[];
    char*  Ahi = smc + OFF_AHI;
    char*  Alo = smc + OFF_ALO;
    char*  Bhi = smc + OFF_BHI;
    float* hs  = (float*)(smc + OFF_HS);
    unsigned int sbase = s2u(smc);

    const int tid = threadIdx.x;
    const int nblk = blockIdx.x * 128;
    const bool horizon = (flags & 1) != 0;
    const bool wrHw = (flags & 2) != 0;
    const bool hz = (flags & 4) != 0;
    const float* hsrc = horizon ? g_hw : g_h;
    const unsigned char* me = g_meff + (size_t)t * NN;
    const unsigned char* mk = g_maskc + (size_t)t * NN;

    const int w = tid >> 5, l = tid & 31;
    const int m0 = (w & 3) * 32, n0 = (w >> 2) * 32;
    const int fg = l >> 2, fc = l & 3;

    // ---- staging: kick off B gate-z via cp.async, then A/hs via regs ----
    stageB_async(sbase, 0, tid);
    {
        int row = tid >> 2, q = tid & 3;
        int nA = nblk + row;
        bool rowValid = nA < NN;
        bool rowOn = rowValid && (horizon || (me[nA] != 0));
        char* arow_h = Ahi + row * ROWB;
        char* arow_l = Alo + row * ROWB;
#pragma unroll
        for (int g8 = 0; g8 < 8; ++g8) {
            int k0 = q * 32 + g8 * 4;
            float4 v = make_float4(0.f, 0.f, 0.f, 0.f);
            if (rowOn) v = *(const float4*)(hsrc + (size_t)nA * HH + k0);
            hs[row * 129 + k0 + 0] = v.x;
            hs[row * 129 + k0 + 1] = v.y;
            hs[row * 129 + k0 + 2] = v.z;
            hs[row * 129 + k0 + 3] = v.w;
            float xh = bfr(v.x), yh = bfr(v.y), zh = bfr(v.z), wh = bfr(v.w);
            *(unsigned int*)(arow_h + k0 * 2)     = pkbf(xh, yh);
            *(unsigned int*)(arow_h + k0 * 2 + 4) = pkbf(zh, wh);
            *(unsigned int*)(arow_l + k0 * 2)     = pkbf(v.x - xh, v.y - yh);
            *(unsigned int*)(arow_l + k0 * 2 + 4) = pkbf(v.z - zh, v.w - wh);
        }
        {
            float4 v = make_float4(0.f, 0.f, 0.f, 0.f);
            if (rowValid) v = *(const float4*)(agg + (size_t)nA * 16 + 4 * q);
            int kb = (128 + q * 4) * 2;
            float xh = bfr(v.x), yh = bfr(v.y), zh = bfr(v.z), wh = bfr(v.w);
            *(unsigned int*)(arow_h + kb)     = pkbf(xh, yh);
            *(unsigned int*)(arow_h + kb + 4) = pkbf(zh, wh);
            *(unsigned int*)(arow_l + kb)     = pkbf(v.x - xh, v.y - yh);
            *(unsigned int*)(arow_l + kb + 4) = pkbf(v.z - zh, v.w - wh);
        }
    }
    CPA_WAIT();
    __syncthreads();

    unsigned int aHiAd = sbase + OFF_AHI + (m0 + (l & 15)) * ROWB + (l >> 4) * 16;
    unsigned int aLoAd = aHiAd + (OFF_ALO - OFF_AHI);
    unsigned int bHiAd = sbase + OFF_BHI +
                         (n0 + (l >> 4) * 8 + (l & 7)) * ROWB + ((l >> 3) & 1) * 16;
    unsigned int bLoAd = bHiAd + (OFF_BLO - OFF_BHI);
    const int kt0 = hz ? 8 : 0;

    float dd[32];
    float zreg[32];

#define GATE_MMA()                                                          \
    _Pragma("unroll") for (int j = 0; j < 32; ++j) dd[j] = 0.f;             \
    for (int kt = kt0; kt < 9; ++kt) {                                      \
        unsigned int ah[2][4], al[2][4], bh[2][4], bl[2][4];                \
        ldm4(ah[0], aHiAd + kt * 32);                                       \
        ldm4(ah[1], aHiAd + kt * 32 + 16 * ROWB);                           \
        ldm4(al[0], aLoAd + kt * 32);                                       \
        ldm4(al[1], aLoAd + kt * 32 + 16 * ROWB);                           \
        ldm4(bh[0], bHiAd + kt * 32);                                       \
        ldm4(bh[1], bHiAd + kt * 32 + 16 * ROWB);                           \
        ldm4(bl[0], bLoAd + kt * 32);                                       \
        ldm4(bl[1], bLoAd + kt * 32 + 16 * ROWB);                           \
        _Pragma("unroll") for (int am = 0; am < 2; ++am)                    \
        _Pragma("unroll") for (int bn = 0; bn < 4; ++bn) {                  \
            float* dp = dd + (am * 4 + bn) * 4;                             \
            const unsigned int* bhp = &bh[bn >> 1][(bn & 1) * 2];           \
            const unsigned int* blp = &bl[bn >> 1][(bn & 1) * 2];           \
            mma_bf(dp, ah[am], bhp);                                        \
            mma_bf(dp, ah[am], blp);                                        \
            mma_bf(dp, al[am], bhp);                                        \
        }                                                                   \
    }

    // ================= gate Z =================
    GATE_MMA();
    __syncthreads();                     // all warps done with B(z)
    stageB_async(sbase, 1, tid);         // prefetch B(r) under z epilogue
#pragma unroll
    for (int am = 0; am < 2; ++am)
#pragma unroll
    for (int bn = 0; bn < 4; ++bn)
#pragma unroll
    for (int e = 0; e < 4; ++e) {
        int idx = (am * 4 + bn) * 4 + e;
        int col = n0 + 8 * bn + 2 * fc + (e & 1);
        zreg[idx] = sigmoidf_(dd[idx] + g_bzr[col]);
    }
    CPA_WAIT();
    __syncthreads();

    // ================= gate R =================
    GATE_MMA();
    __syncthreads();                     // all warps done with B(r) and A
    stageB_async(sbase, 2, tid);         // prefetch B(h) under hr epilogue
#pragma unroll
    for (int am = 0; am < 2; ++am)
#pragma unroll
    for (int bn = 0; bn < 4; ++bn)
#pragma unroll
    for (int eh = 0; eh < 2; ++eh) {
        int idx = (am * 4 + bn) * 4 + eh * 2;
        int row = m0 + 16 * am + fg + eh * 8;
        int cb = n0 + 8 * bn + 2 * fc;
        float r0 = sigmoidf_(dd[idx]     + g_bzr[128 + cb]);
        float r1 = sigmoidf_(dd[idx + 1] + g_bzr[128 + cb + 1]);
        if (!hz) {
            float p0 = hs[row * 129 + cb] * r0;
            float p1 = hs[row * 129 + cb + 1] * r1;
            float p0h = bfr(p0), p1h = bfr(p1);
            *(unsigned int*)(Ahi + row * ROWB + cb * 2) = pkbf(p0h, p1h);
            *(unsigned int*)(Alo + row * ROWB + cb * 2) = pkbf(p0 - p0h, p1 - p1h);
        }
    }
    CPA_WAIT();
    __syncthreads();

    // ================= gate H + combine =================
    GATE_MMA();
#pragma unroll
    for (int am = 0; am < 2; ++am)
#pragma unroll
    for (int bn = 0; bn < 4; ++bn)
#pragma unroll
    for (int e = 0; e < 4; ++e) {
        int idx = (am * 4 + bn) * 4 + e;
        int row = m0 + 16 * am + fg + (e >> 1) * 8;
        int col = n0 + 8 * bn + 2 * fc + (e & 1);
        float ht = tanhf_(dd[idx] + g_bh[col]);
        float z = zreg[idx];
        float h0 = hs[row * 129 + col];
        hs[row * 129 + col] = z * h0 + (1.f - z) * ht;
    }
    __syncthreads();

    if (horizon && tid < 96) {
        float4 wv = *(const float4*)(headW + tid * 4);
        ((float*)Bhi)[tid * 4 + 0] = wv.x; ((float*)Bhi)[tid * 4 + 1] = wv.y;
        ((float*)Bhi)[tid * 4 + 2] = wv.z; ((float*)Bhi)[tid * 4 + 3] = wv.w;
    }

    // ---- coalesced masked writeback ----
    {
        int row = tid >> 2, cg = (tid & 3) * 32;
        int n = nblk + row;
        if (n < NN) {
            bool wr = horizon ? true : (mk[n] != 0);
#pragma unroll
            for (int i4 = 0; i4 < 8; ++i4) {
                float4 v;
                v.x = hs[row * 129 + cg + 4 * i4 + 0];
                v.y = hs[row * 129 + cg + 4 * i4 + 1];
                v.z = hs[row * 129 + cg + 4 * i4 + 2];
                v.w = hs[row * 129 + cg + 4 * i4 + 3];
                if (horizon) {
                    *(float4*)(g_hw + (size_t)n * HH + cg + 4 * i4) = v;
                } else {
                    if (wr) *(float4*)(g_h + (size_t)n * HH + cg + 4 * i4) = v;
                    if (wrHw) {
                        float4 vz = wr ? v : make_float4(0.f, 0.f, 0.f, 0.f);
                        *(float4*)(g_hw + (size_t)n * HH + cg + 4 * i4) = vz;
                    }
                }
            }
        }
    }

    // ---- fused head prediction (horizon): 4 threads per node + shfl reduce ----
    if (horizon) {
        __syncthreads();
        int row = tid >> 2, pp = tid & 3;
        int n = nblk + row;
        const float* hwv = (const float*)Bhi;
        float p0 = 0.f, p1 = 0.f, p2 = 0.f;
        int c0 = pp * 32;
#pragma unroll 8
        for (int c = c0; c < c0 + 32; ++c) {
            float hv = hs[row * 129 + c];
            p0 += hv * hwv[c * 3 + 0];
            p1 += hv * hwv[c * 3 + 1];
            p2 += hv * hwv[c * 3 + 2];
        }
#pragma unroll
        for (int o = 2; o >= 1; o >>= 1) {
            p0 += __shfl_down_sync(0xFFFFFFFFu, p0, o, 4);
            p1 += __shfl_down_sync(0xFFFFFFFFu, p1, o, 4);
            p2 += __shfl_down_sync(0xFFFFFFFFu, p2, o, 4);
        }
        if (pp == 0 && n < NN) {
            p0 += headb[0]; p1 += headb[1]; p2 += headb[2];
            outk[n * 3 + 0] = p0;
            outk[n * 3 + 1] = p1;
            outk[n * 3 + 2] = p2;
            float di = g_dinv_all[11 * NN + n];
            float s = di * di;
            agghN[n * FF + 0] = s * p0;
            agghN[n * FF + 1] = s * p1;
            agghN[n * FF + 2] = s * p2;
        }
    }
}

// ---------------- transition / horizon helpers ----------------
// copies only cols 3..15 (cols 0..2 are owned by agghN / scatter3)
__global__ void k_transition(const float* __restrict__ agg11) {
    int i = blockIdx.x * blockDim.x + threadIdx.x;
    if (i >= NN * FF) return;
    if ((i & 15) < 3) return;
    float v = agg11[i];
    g_aggh[i] = v;
    g_aggh[NN * FF + i] = v;
}
__global__ void k_scatter3(const int* __restrict__ ei11,
                           const float* __restrict__ pred,
                           float* __restrict__ target) {
    int e = blockIdx.x * blockDim.x + threadIdx.x;
    if (e >= EE) return;
    int s = ei11[e], d = ei11[EE + e];
    float nrm = g_nrm11[e];
    float p0 = pred[s * 3 + 0], p1 = pred[s * 3 + 1], p2 = pred[s * 3 + 2];
    float* o = target + (size_t)d * FF;
    REDV2(o, nrm * p0, nrm * p1);
    RED1(o + 2, nrm * p2);
}

// ---------------- launch ----------------
extern "C" void kernel_launch(void* const* d_in, const int* in_sizes, int n_in,
                              void* d_out, int out_size) {
    const float* x_seq = (const float*)d_in[0];
    const int*   ei    = (const int*)d_in[1];
    const float* ea    = (const float*)d_in[2];
    const unsigned char* mraw = (const unsigned char*)d_in[3];
    const float* Wcz = (const float*)d_in[4];
    const float* bcz = (const float*)d_in[5];
    const float* Wlz = (const float*)d_in[6];
    const float* blz = (const float*)d_in[7];
    const float* Wcr = (const float*)d_in[8];
    const float* bcr = (const float*)d_in[9];
    const float* Wlr = (const float*)d_in[10];
    const float* blr = (const float*)d_in[11];
    const float* Wch = (const float*)d_in[12];
    const float* bch = (const float*)d_in[13];
    const float* Wlh = (const float*)d_in[14];
    const float* blh = (const float*)d_in[15];
    const float* hW  = (const float*)d_in[16];
    const float* hb  = (const float*)d_in[17];
    float* out = (float*)d_out;

    void* p;
    cudaGetSymbolAddress(&p, g_agg_all);
    const float* agg_all = (const float*)p;
    cudaGetSymbolAddress(&p, g_aggh);
    float* aggh = (float*)p;

    static int s_init_done = 0;
    static cudaStream_t s2;
    static cudaEvent_t evFork;
    static cudaEvent_t evT[TT];
    static cudaEvent_t evTr;
    if (!s_init_done) {
        cudaFuncSetAttribute(k_cell, cudaFuncAttributeMaxDynamicSharedMemorySize,
                             SMEM_CELL);
        cudaStreamCreateWithFlags(&s2, cudaStreamNonBlocking);
        cudaEventCreateWithFlags(&evFork, cudaEventDisableTiming);
        cudaEventCreateWithFlags(&evTr, cudaEventDisableTiming);
        for (int t = 0; t < TT; ++t)
            cudaEventCreateWithFlags(&evT[t], cudaEventDisableTiming);
        s_init_done = 1;
    }

    const int THR = 256;
    const float* Wlh_bot = Wlh + 128 * 128;

    // ---- shared prologue (main) ----
    k_detect<<<1, THR>>>(mraw);
    k_convert<<<(NN + THR - 1) / THR, THR>>>(mraw);
    k_fuse<<<(6528 + 128 * 256 + THR - 1) / THR, THR>>>(Wcz, Wlz, blz, bcz,
                                                        Wcr, Wlr, blr, bcr,
                                                        Wch, Wlh, blh, bch);
    k_fuse2<<<(3 * KTOT * 128 + THR - 1) / THR, THR>>>(Wlh_bot);
    k_init<<<(NN * HH + THR - 1) / THR, THR>>>();

    // ---- fork: t=0 chain on main; t=1..11 interleaved per-t chains on s2 ----
    cudaEventRecord(evFork, 0);
    cudaStreamWaitEvent(s2, evFork, 0);

    k_deg_rng<<<(EE + THR - 1) / THR, THR>>>(ei, ea, 0, 1);
    k_dinv_rng<<<(NN + THR - 1) / THR, THR>>>(0, 1);
    k_aggself_rng<<<(NN + THR - 1) / THR, THR>>>(x_seq, 0, 1);
    k_scatter_one<<<(EE + THR - 1) / THR, THR>>>(ei, ea, x_seq, 0);

    const float* agg11 = agg_all + (size_t)11 * NN * FF;
    for (int t = 1; t < TT; ++t) {
        k_deg_rng<<<(EE + THR - 1) / THR, THR, 0, s2>>>(ei, ea, t, 1);
        k_dinv_rng<<<(NN + THR - 1) / THR, THR, 0, s2>>>(t, 1);
        k_aggself_rng<<<(NN + THR - 1) / THR, THR, 0, s2>>>(x_seq, t, 1);
        k_scatter_one<<<(EE + THR - 1) / THR, THR, 0, s2>>>(ei, ea, x_seq, t);
        cudaEventRecord(evT[t], s2);
    }
    k_transition<<<(NN * FF + THR - 1) / THR, THR, 0, s2>>>(agg11);
    cudaEventRecord(evTr, s2);

    dim3 gC((NN + 127) / 128);

    for (int t = 0; t < TT; ++t) {
        if (t > 0) cudaStreamWaitEvent(0, evT[t], 0);
        const float* aggt = agg_all + (size_t)t * NN * FF;
        int flags = (t == 11) ? 2 : 0;
        if (t == 0) flags |= 4;
        k_cell<<<gC, THR_CELL, SMEM_CELL>>>(aggt, t, flags, hW, hb,
                                            nullptr, nullptr);
    }

    cudaStreamWaitEvent(0, evTr, 0);
    const int* eiL = ei + (size_t)11 * 2 * EE;

    for (int k = 0; k < HOR; ++k) {
        const float* aggk = (k == 0) ? agg11 : (aggh + (size_t)(k & 1) * NN * FF);
        float* agghN = aggh + (size_t)((k + 1) & 1) * NN * FF;
        if (k > 0) {
            const float* predPrev = out + (size_t)(k - 1) * NN * OUTD;
            k_scatter3<<<(EE + THR - 1) / THR, THR>>>(
                eiL, predPrev, aggh + (size_t)(k & 1) * NN * FF);
        }
        k_cell<<<gC, THR_CELL, SMEM_CELL>>>(aggk, 11, 1, hW, hb,
                                            out + (size_t)k * NN * OUTD, agghN);
    }
}

// round 16
// speedup vs baseline: 1.1898x; 1.0199x over previous
#include <cuda_runtime.h>
#include <cuda_bf16.h>
#include <math.h>

#define NN 50000
#define EE 1600000
#define TT 12
#define FF 16
#define HH 128
#define OUTD 3
#define HOR 6

#define KTOT 144            // 128 (h) + 16 (agg)
#define ASTRIDE 152         // bf16 units per row (304 B) -> conflict-free ldmatrix
#define ROWB (ASTRIDE * 2)  // 304 bytes

// smem layout (bytes)
#define OFF_AHI 0
#define OFF_ALO 38912
#define OFF_BHI 77824
#define OFF_BLO 116736
#define OFF_HS  155648      // hs fp32 [128][129]
#define SMEM_CELL (155648 + 128 * 129 * 4)   // 221696

#define THR_CELL 512

// ---------------- scratch ----------------
__device__ float g_dinv_all[TT * NN];
__device__ float g_agg_all[(size_t)TT * NN * FF];
__device__ float g_aggh[2 * NN * FF];
__device__ float g_nrm11[EE];
__device__ float g_h[NN * HH];
__device__ float g_hw[NN * HH];
__device__ unsigned char g_maskc[TT * NN];
__device__ unsigned char g_meff[TT * NN];
__device__ float g_Bzr_top[16 * 256];
__device__ float g_bzr[256];
__device__ float g_Bzr_bot[128 * 256];
__device__ float g_Bh_top[16 * 128];
__device__ float g_bh[128];
__device__ int g_isbyte;
// bf16 weight splits, [n][ASTRIDE] row-major (k contiguous), per gate {z,r,h}
__device__ __align__(16) unsigned short g_Bsp_hi[3][128 * ASTRIDE];
__device__ __align__(16) unsigned short g_Bsp_lo[3][128 * ASTRIDE];

// ---------------- helpers ----------------
__device__ __forceinline__ unsigned int s2u(const void* p) {
    unsigned int a;
    asm("{ .reg .u64 t; cvta.to.shared.u64 t, %1; cvt.u32.u64 %0, t; }"
        : "=r"(a) : "l"(p));
    return a;
}
__device__ __forceinline__ float bfr(float x) {
    return __bfloat162float(__float2bfloat16_rn(x));
}
__device__ __forceinline__ unsigned int pkbf(float lo, float hi) {  // lo -> low half
    unsigned int r;
    asm("cvt.rn.bf16x2.f32 %0, %1, %2;" : "=r"(r) : "f"(hi), "f"(lo));
    return r;
}
__device__ __forceinline__ void ldm4(unsigned int* r, unsigned int addr) {
    asm volatile("ldmatrix.sync.aligned.m8n8.x4.shared.b16 {%0,%1,%2,%3}, [%4];"
        : "=r"(r[0]), "=r"(r[1]), "=r"(r[2]), "=r"(r[3]) : "r"(addr));
}
__device__ __forceinline__ void mma_bf(float* d, const unsigned int* a,
                                       const unsigned int* b) {
    asm volatile(
        "mma.sync.aligned.m16n8k16.row.col.f32.bf16.bf16.f32 "
        "{%0,%1,%2,%3}, {%4,%5,%6,%7}, {%8,%9}, {%0,%1,%2,%3};"
        : "+f"(d[0]), "+f"(d[1]), "+f"(d[2]), "+f"(d[3])
        : "r"(a[0]), "r"(a[1]), "r"(a[2]), "r"(a[3]), "r"(b[0]), "r"(b[1]));
}
__device__ __forceinline__ float sigmoidf_(float v) {
    return __fdividef(1.0f, 1.0f + __expf(-v));
}
__device__ __forceinline__ float tanhf_(float v) {
    float e = __expf(2.0f * v);
    return 1.0f - __fdividef(2.0f, e + 1.0f);
}
#define CPA16(saddr, gptr) \
    asm volatile("cp.async.cg.shared.global [%0], [%1], 16;" \
                 :: "r"(saddr), "l"(gptr) : "memory")
#define CPA_COMMIT() asm volatile("cp.async.commit_group;" ::: "memory")
#define CPA_WAIT()   asm volatile("cp.async.wait_group 0;" ::: "memory")

__device__ __forceinline__ void stageB_async(unsigned int sbase, int gate, int tid) {
    const char* sh = (const char*)g_Bsp_hi[gate];
    const char* sl = (const char*)g_Bsp_lo[gate];
    unsigned int dh = sbase + OFF_BHI;
    unsigned int dl = sbase + OFF_BLO;
    for (int i = tid; i < 128 * ASTRIDE / 8; i += THR_CELL) {
        CPA16(dh + i * 16, sh + i * 16);
        CPA16(dl + i * 16, sl + i * 16);
    }
    CPA_COMMIT();
}

// ---------------- mask detection / conversion ----------------
__global__ void k_detect(const unsigned char* raw) {
    __shared__ int cnt;
    if (threadIdx.x == 0) cnt = 0;
    __syncthreads();
    int c = 0;
    for (int i = threadIdx.x; i < 4096; i += blockDim.x) c += (raw[i] != 0);
    atomicAdd(&cnt, c);
    __syncthreads();
    if (threadIdx.x == 0) g_isbyte = (cnt > 2048) ? 1 : 0;
}
__global__ void k_convert(const unsigned char* raw) {
    int n = blockIdx.x * blockDim.x + threadIdx.x;
    if (n >= NN) return;
    int isb = g_isbyte, seen = 0;
#pragma unroll
    for (int t = 0; t < TT; ++t) {
        int m = isb ? (raw[t * NN + n] != 0) : (((const int*)raw)[t * NN + n] != 0);
        g_maskc[t * NN + n] = (unsigned char)m;
        g_meff[t * NN + n] = (unsigned char)(m & seen);
        seen |= m;
    }
}

// ---------------- weight fusion ----------------
__global__ void k_fuse(const float* __restrict__ Wcz, const float* __restrict__ Wlz,
                       const float* __restrict__ blz, const float* __restrict__ bcz,
                       const float* __restrict__ Wcr, const float* __restrict__ Wlr,
                       const float* __restrict__ blr, const float* __restrict__ bcr,
                       const float* __restrict__ Wch, const float* __restrict__ Wlh,
                       const float* __restrict__ blh, const float* __restrict__ bch) {
    int i = blockIdx.x * blockDim.x + threadIdx.x;
    if (i < 16 * 256) {
        int k = i / 256, c = i % 256, cc = c & 127;
        const float* A = (c < 128) ? Wcz : Wcr;
        const float* B = (c < 128) ? Wlz : Wlr;
        float s = 0.f;
        for (int j = 0; j < 128; ++j) s += A[k * 128 + j] * B[j * 128 + cc];
        g_Bzr_top[i] = s;
    } else if (i < 4096 + 2048) {
        int r = i - 4096; int k = r / 128, c = r % 128;
        float s = 0.f;
        for (int j = 0; j < 128; ++j) s += Wch[k * 128 + j] * Wlh[j * 128 + c];
        g_Bh_top[r] = s;
    } else if (i < 6144 + 256) {
        int c = i - 6144; int cc = c & 127;
        const float* bc = (c < 128) ? bcz : bcr;
        const float* B  = (c < 128) ? Wlz : Wlr;
        const float* bl = (c < 128) ? blz : blr;
        float s = bl[cc];
        for (int j = 0; j < 128; ++j) s += bc[j] * B[j * 128 + cc];
        g_bzr[c] = s;
    } else if (i < 6400 + 128) {
        int c = i - 6400;
        float s = blh[c];
        for (int j = 0; j < 128; ++j) s += bch[j] * Wlh[j * 128 + c];
        g_bh[c] = s;
    } else if (i < 6528 + 128 * 256) {
        int r = i - 6528; int k = r / 256, c = r % 256;
        g_Bzr_bot[r] = (c < 128) ? Wlz[(128 + k) * 128 + c]
                                 : Wlr[(128 + k) * 128 + (c - 128)];
    }
}

__global__ void k_fuse2(const float* __restrict__ Wlh_bot) {
    int i = blockIdx.x * blockDim.x + threadIdx.x;
    if (i >= 3 * KTOT * 128) return;
    int g = i / (KTOT * 128), r = i - g * (KTOT * 128);
    int k = r / 128, n = r - k * 128;
    float w;
    if (k < 128) {
        if (g == 0)      w = g_Bzr_bot[k * 256 + n];
        else if (g == 1) w = g_Bzr_bot[k * 256 + 128 + n];
        else             w = Wlh_bot[k * 128 + n];
    } else {
        int kt = k - 128;
        if (g == 0)      w = g_Bzr_top[kt * 256 + n];
        else if (g == 1) w = g_Bzr_top[kt * 256 + 128 + n];
        else             w = g_Bh_top[kt * 128 + n];
    }
    float wh = bfr(w);
    g_Bsp_hi[g][n * ASTRIDE + k] = __bfloat16_as_ushort(__float2bfloat16_rn(wh));
    g_Bsp_lo[g][n * ASTRIDE + k] = __bfloat16_as_ushort(__float2bfloat16_rn(w - wh));
}

__global__ void k_init() {
    int i = blockIdx.x * blockDim.x + threadIdx.x;
    if (i < NN * HH) g_h[i] = 0.f;
    if (i < TT * NN) g_dinv_all[i] = 0.f;
}

// ---------------- degree / aggregation (t-ranged) ----------------
__global__ void k_deg_rng(const int* __restrict__ ei, const float* __restrict__ ea,
                          int t0, int nt) {
    int e = blockIdx.x * blockDim.x + threadIdx.x;
    if (e >= nt * EE) return;
    int t = t0 + e / EE, le = e % EE;
    int dst = ei[(size_t)t * 2 * EE + EE + le];
    atomicAdd(&g_dinv_all[t * NN + dst], ea[(size_t)t * EE + le]);
}
__global__ void k_dinv_rng(int t0, int nt) {
    int i = blockIdx.x * blockDim.x + threadIdx.x;
    if (i >= nt * NN) return;
    int idx = t0 * NN + i;
    g_dinv_all[idx] = rsqrtf(g_dinv_all[idx] + 1.0f);
}
__global__ void k_aggself_rng(const float* __restrict__ x_seq, int t0, int nt) {
    int i = blockIdx.x * blockDim.x + threadIdx.x;
    if (i >= nt * NN) return;
    int t = t0 + i / NN, n = i % NN;
    float di = g_dinv_all[t * NN + n];
    float s = di * di;
    const float4* xp = (const float4*)(x_seq + (size_t)t * NN * FF + (size_t)n * FF);
    float4* op = (float4*)(g_agg_all + (size_t)t * NN * FF + (size_t)n * FF);
    float4 a = xp[0], b = xp[1], c = xp[2], d = xp[3];
    op[0] = make_float4(s * a.x, s * a.y, s * a.z, s * a.w);
    op[1] = make_float4(s * b.x, s * b.y, s * b.z, s * b.w);
    op[2] = make_float4(s * c.x, s * c.y, s * c.z, s * c.w);
    op[3] = make_float4(s * d.x, s * d.y, s * d.z, s * d.w);
}
#define REDV4(p, a, b, c, d)                                              \
    asm volatile("red.global.add.v4.f32 [%0], {%1,%2,%3,%4};"             \
                 :: "l"(p), "f"(a), "f"(b), "f"(c), "f"(d) : "memory")
__global__ void k_scatter_one(const int* __restrict__ ei, const float* __restrict__ ea,
                              const float* __restrict__ x_seq, int t) {
    int le = blockIdx.x * blockDim.x + threadIdx.x;
    if (le >= EE) return;
    const int* eit = ei + (size_t)t * 2 * EE;
    int s = eit[le], d = eit[EE + le];
    const float* dinv = g_dinv_all + t * NN;
    float nrm = dinv[s] * ea[(size_t)t * EE + le] * dinv[d];
    if (t == 11) g_nrm11[le] = nrm;
    const float4* xp = (const float4*)(x_seq + (size_t)t * NN * FF + (size_t)s * FF);
    float4 a = xp[0], b = xp[1], c = xp[2], dd = xp[3];
    float* o = g_agg_all + (size_t)t * NN * FF + (size_t)d * FF;
    REDV4(o + 0,  nrm * a.x,  nrm * a.y,  nrm * a.z,  nrm * a.w);
    REDV4(o + 4,  nrm * b.x,  nrm * b.y,  nrm * b.z,  nrm * b.w);
    REDV4(o + 8,  nrm * c.x,  nrm * c.y,  nrm * c.z,  nrm * c.w);
    REDV4(o + 12, nrm * dd.x, nrm * dd.y, nrm * dd.z, nrm * dd.w);
}

// ---------------- fused TGCN cell: mma.sync bf16 split GEMMs ----------------
// HZ: h_eff known all-zero (t=0) -> only the agg k-tile contributes
// flags: bit0 = horizon, bit1 = write g_hw = mk ? hn : 0 (t==11)
template <bool HZ>
__global__ __launch_bounds__(THR_CELL, 1)
void k_cell(const float* __restrict__ agg, int t, int flags,
            const float* __restrict__ headW, const float* __restrict__ headb,
            float* __restrict__ outk, float* __restrict__ agghN) {
    extern __shared__ __align__(16) char smc[];
    char*  Ahi = smc + OFF_AHI;
    char*  Alo = smc + OFF_ALO;
    char*  Bhi = smc + OFF_BHI;
    float* hs  = (float*)(smc + OFF_HS);
    unsigned int sbase = s2u(smc);

    const int tid = threadIdx.x;
    const int nblk = blockIdx.x * 128;
    const bool horizon = (flags & 1) != 0;
    const bool wrHw = (flags & 2) != 0;
    const float* hsrc = horizon ? g_hw : g_h;
    const unsigned char* me = g_meff + (size_t)t * NN;
    const unsigned char* mk = g_maskc + (size_t)t * NN;

    const int w = tid >> 5, l = tid & 31;
    const int m0 = (w & 3) * 32, n0 = (w >> 2) * 32;
    const int fg = l >> 2, fc = l & 3;

    // ---- staging: kick off B gate-z via cp.async, then A/hs via regs ----
    stageB_async(sbase, 0, tid);
    {
        int row = tid >> 2, q = tid & 3;
        int nA = nblk + row;
        bool rowValid = nA < NN;
        bool rowOn = rowValid && (horizon || (me[nA] != 0));
        char* arow_h = Ahi + row * ROWB;
        char* arow_l = Alo + row * ROWB;
#pragma unroll
        for (int g8 = 0; g8 < 8; ++g8) {
            int k0 = q * 32 + g8 * 4;
            float4 v = make_float4(0.f, 0.f, 0.f, 0.f);
            if (rowOn) v = *(const float4*)(hsrc + (size_t)nA * HH + k0);
            hs[row * 129 + k0 + 0] = v.x;
            hs[row * 129 + k0 + 1] = v.y;
            hs[row * 129 + k0 + 2] = v.z;
            hs[row * 129 + k0 + 3] = v.w;
            float xh = bfr(v.x), yh = bfr(v.y), zh = bfr(v.z), wh = bfr(v.w);
            *(unsigned int*)(arow_h + k0 * 2)     = pkbf(xh, yh);
            *(unsigned int*)(arow_h + k0 * 2 + 4) = pkbf(zh, wh);
            *(unsigned int*)(arow_l + k0 * 2)     = pkbf(v.x - xh, v.y - yh);
            *(unsigned int*)(arow_l + k0 * 2 + 4) = pkbf(v.z - zh, v.w - wh);
        }
        {
            float4 v = make_float4(0.f, 0.f, 0.f, 0.f);
            if (rowValid) v = *(const float4*)(agg + (size_t)nA * 16 + 4 * q);
            int kb = (128 + q * 4) * 2;
            float xh = bfr(v.x), yh = bfr(v.y), zh = bfr(v.z), wh = bfr(v.w);
            *(unsigned int*)(arow_h + kb)     = pkbf(xh, yh);
            *(unsigned int*)(arow_h + kb + 4) = pkbf(zh, wh);
            *(unsigned int*)(arow_l + kb)     = pkbf(v.x - xh, v.y - yh);
            *(unsigned int*)(arow_l + kb + 4) = pkbf(v.z - zh, v.w - wh);
        }
    }
    CPA_WAIT();
    __syncthreads();

    unsigned int aHiAd = sbase + OFF_AHI + (m0 + (l & 15)) * ROWB + (l >> 4) * 16;
    unsigned int aLoAd = aHiAd + (OFF_ALO - OFF_AHI);
    unsigned int bHiAd = sbase + OFF_BHI +
                         (n0 + (l >> 4) * 8 + (l & 7)) * ROWB + ((l >> 3) & 1) * 16;
    unsigned int bLoAd = bHiAd + (OFF_BLO - OFF_BHI);

    float dd[32];
    float zreg[32];

#define MMA_KT(kt)                                                          \
    {                                                                       \
        unsigned int ah[2][4], al[2][4], bh[2][4], bl[2][4];                \
        ldm4(ah[0], aHiAd + (kt) * 32);                                     \
        ldm4(ah[1], aHiAd + (kt) * 32 + 16 * ROWB);                         \
        ldm4(al[0], aLoAd + (kt) * 32);                                     \
        ldm4(al[1], aLoAd + (kt) * 32 + 16 * ROWB);                         \
        ldm4(bh[0], bHiAd + (kt) * 32);                                     \
        ldm4(bh[1], bHiAd + (kt) * 32 + 16 * ROWB);                         \
        ldm4(bl[0], bLoAd + (kt) * 32);                                     \
        ldm4(bl[1], bLoAd + (kt) * 32 + 16 * ROWB);                         \
        _Pragma("unroll") for (int am = 0; am < 2; ++am)                    \
        _Pragma("unroll") for (int bn = 0; bn < 4; ++bn) {                  \
            float* dp = dd + (am * 4 + bn) * 4;                             \
            const unsigned int* bhp = &bh[bn >> 1][(bn & 1) * 2];           \
            const unsigned int* blp = &bl[bn >> 1][(bn & 1) * 2];           \
            mma_bf(dp, ah[am], bhp);                                        \
            mma_bf(dp, ah[am], blp);                                        \
            mma_bf(dp, al[am], bhp);                                        \
        }                                                                   \
    }

#define GATE_MMA()                                                          \
    _Pragma("unroll") for (int j = 0; j < 32; ++j) dd[j] = 0.f;             \
    if (HZ) { MMA_KT(8); }                                                  \
    else {                                                                  \
        _Pragma("unroll")                                                   \
        for (int kt = 0; kt < 9; ++kt) { MMA_KT(kt); }                      \
    }

    // ================= gate Z =================
    GATE_MMA();
    __syncthreads();                     // all warps done with B(z)
    stageB_async(sbase, 1, tid);         // prefetch B(r) under z epilogue
#pragma unroll
    for (int am = 0; am < 2; ++am)
#pragma unroll
    for (int bn = 0; bn < 4; ++bn)
#pragma unroll
    for (int e = 0; e < 4; ++e) {
        int idx = (am * 4 + bn) * 4 + e;
        int col = n0 + 8 * bn + 2 * fc + (e & 1);
        zreg[idx] = sigmoidf_(dd[idx] + g_bzr[col]);
    }
    CPA_WAIT();
    __syncthreads();

    // ================= gate R =================
    GATE_MMA();
    __syncthreads();                     // all warps done with B(r) and A
    stageB_async(sbase, 2, tid);         // prefetch B(h) under hr epilogue
#pragma unroll
    for (int am = 0; am < 2; ++am)
#pragma unroll
    for (int bn = 0; bn < 4; ++bn)
#pragma unroll
    for (int eh = 0; eh < 2; ++eh) {
        int idx = (am * 4 + bn) * 4 + eh * 2;
        int row = m0 + 16 * am + fg + eh * 8;
        int cb = n0 + 8 * bn + 2 * fc;
        float r0 = sigmoidf_(dd[idx]     + g_bzr[128 + cb]);
        float r1 = sigmoidf_(dd[idx + 1] + g_bzr[128 + cb + 1]);
        if (!HZ) {
            float p0 = hs[row * 129 + cb] * r0;
            float p1 = hs[row * 129 + cb + 1] * r1;
            float p0h = bfr(p0), p1h = bfr(p1);
            *(unsigned int*)(Ahi + row * ROWB + cb * 2) = pkbf(p0h, p1h);
            *(unsigned int*)(Alo + row * ROWB + cb * 2) = pkbf(p0 - p0h, p1 - p1h);
        }
    }
    CPA_WAIT();
    __syncthreads();

    // ================= gate H + combine =================
    GATE_MMA();
#pragma unroll
    for (int am = 0; am < 2; ++am)
#pragma unroll
    for (int bn = 0; bn < 4; ++bn)
#pragma unroll
    for (int e = 0; e < 4; ++e) {
        int idx = (am * 4 + bn) * 4 + e;
        int row = m0 + 16 * am + fg + (e >> 1) * 8;
        int col = n0 + 8 * bn + 2 * fc + (e & 1);
        float ht = tanhf_(dd[idx] + g_bh[col]);
        float z = zreg[idx];
        float h0 = hs[row * 129 + col];
        hs[row * 129 + col] = z * h0 + (1.f - z) * ht;
    }
    __syncthreads();

    if (horizon && tid < 96) {
        float4 wv = *(const float4*)(headW + tid * 4);
        ((float*)Bhi)[tid * 4 + 0] = wv.x; ((float*)Bhi)[tid * 4 + 1] = wv.y;
        ((float*)Bhi)[tid * 4 + 2] = wv.z; ((float*)Bhi)[tid * 4 + 3] = wv.w;
    }

    // ---- coalesced masked writeback ----
    {
        int row = tid >> 2, cg = (tid & 3) * 32;
        int n = nblk + row;
        if (n < NN) {
            bool wr = horizon ? true : (mk[n] != 0);
#pragma unroll
            for (int i4 = 0; i4 < 8; ++i4) {
                float4 v;
                v.x = hs[row * 129 + cg + 4 * i4 + 0];
                v.y = hs[row * 129 + cg + 4 * i4 + 1];
                v.z = hs[row * 129 + cg + 4 * i4 + 2];
                v.w = hs[row * 129 + cg + 4 * i4 + 3];
                if (horizon) {
                    *(float4*)(g_hw + (size_t)n * HH + cg + 4 * i4) = v;
                } else {
                    if (wr) *(float4*)(g_h + (size_t)n * HH + cg + 4 * i4) = v;
                    if (wrHw) {
                        float4 vz = wr ? v : make_float4(0.f, 0.f, 0.f, 0.f);
                        *(float4*)(g_hw + (size_t)n * HH + cg + 4 * i4) = vz;
                    }
                }
            }
        }
    }

    // ---- fused head prediction (horizon): 4 threads per node + shfl reduce ----
    if (horizon) {
        __syncthreads();
        int row = tid >> 2, pp = tid & 3;
        int n = nblk + row;
        const float* hwv = (const float*)Bhi;
        float p0 = 0.f, p1 = 0.f, p2 = 0.f;
        int c0 = pp * 32;
#pragma unroll 8
        for (int c = c0; c < c0 + 32; ++c) {
            float hv = hs[row * 129 + c];
            p0 += hv * hwv[c * 3 + 0];
            p1 += hv * hwv[c * 3 + 1];
            p2 += hv * hwv[c * 3 + 2];
        }
#pragma unroll
        for (int o = 2; o >= 1; o >>= 1) {
            p0 += __shfl_down_sync(0xFFFFFFFFu, p0, o, 4);
            p1 += __shfl_down_sync(0xFFFFFFFFu, p1, o, 4);
            p2 += __shfl_down_sync(0xFFFFFFFFu, p2, o, 4);
        }
        if (pp == 0 && n < NN) {
            p0 += headb[0]; p1 += headb[1]; p2 += headb[2];
            outk[n * 3 + 0] = p0;
            outk[n * 3 + 1] = p1;
            outk[n * 3 + 2] = p2;
            float di = g_dinv_all[11 * NN + n];
            float s = di * di;
            agghN[n * FF + 0] = s * p0;
            agghN[n * FF + 1] = s * p1;
            agghN[n * FF + 2] = s * p2;
        }
    }
}

// ---------------- transition / horizon helpers ----------------
__global__ void k_transition(const float* __restrict__ agg11) {
    int i = blockIdx.x * blockDim.x + threadIdx.x;
    if (i >= NN * FF) return;
    if ((i & 15) < 3) return;
    float v = agg11[i];
    g_aggh[i] = v;
    g_aggh[NN * FF + i] = v;
}
__global__ void k_scatter3(const int* __restrict__ ei11,
                           const float* __restrict__ pred,
                           float* __restrict__ target) {
    int e = blockIdx.x * blockDim.x + threadIdx.x;
    if (e >= EE) return;
    int s = ei11[e], d = ei11[EE + e];
    float nrm = g_nrm11[e];
    float p0 = pred[s * 3 + 0], p1 = pred[s * 3 + 1], p2 = pred[s * 3 + 2];
    float* o = target + (size_t)d * FF;
    REDV4(o, nrm * p0, nrm * p1, nrm * p2, 0.f);   // col3 += 0 (frozen col, inert)
}

// ---------------- launch ----------------
extern "C" void kernel_launch(void* const* d_in, const int* in_sizes, int n_in,
                              void* d_out, int out_size) {
    const float* x_seq = (const float*)d_in[0];
    const int*   ei    = (const int*)d_in[1];
    const float* ea    = (const float*)d_in[2];
    const unsigned char* mraw = (const unsigned char*)d_in[3];
    const float* Wcz = (const float*)d_in[4];
    const float* bcz = (const float*)d_in[5];
    const float* Wlz = (const float*)d_in[6];
    const float* blz = (const float*)d_in[7];
    const float* Wcr = (const float*)d_in[8];
    const float* bcr = (const float*)d_in[9];
    const float* Wlr = (const float*)d_in[10];
    const float* blr = (const float*)d_in[11];
    const float* Wch = (const float*)d_in[12];
    const float* bch = (const float*)d_in[13];
    const float* Wlh = (const float*)d_in[14];
    const float* blh = (const float*)d_in[15];
    const float* hW  = (const float*)d_in[16];
    const float* hb  = (const float*)d_in[17];
    float* out = (float*)d_out;

    void* p;
    cudaGetSymbolAddress(&p, g_agg_all);
    const float* agg_all = (const float*)p;
    cudaGetSymbolAddress(&p, g_aggh);
    float* aggh = (float*)p;

    static int s_init_done = 0;
    static cudaStream_t s2;
    static cudaEvent_t evFork;
    static cudaEvent_t evT[TT];
    static cudaEvent_t evTr;
    if (!s_init_done) {
        cudaFuncSetAttribute(k_cell<false>,
                             cudaFuncAttributeMaxDynamicSharedMemorySize, SMEM_CELL);
        cudaFuncSetAttribute(k_cell<true>,
                             cudaFuncAttributeMaxDynamicSharedMemorySize, SMEM_CELL);
        cudaStreamCreateWithFlags(&s2, cudaStreamNonBlocking);
        cudaEventCreateWithFlags(&evFork, cudaEventDisableTiming);
        cudaEventCreateWithFlags(&evTr, cudaEventDisableTiming);
        for (int t = 0; t < TT; ++t)
            cudaEventCreateWithFlags(&evT[t], cudaEventDisableTiming);
        s_init_done = 1;
    }

    const int THR = 256;
    const float* Wlh_bot = Wlh + 128 * 128;

    // ---- shared prologue (main) ----
    k_detect<<<1, THR>>>(mraw);
    k_convert<<<(NN + THR - 1) / THR, THR>>>(mraw);
    k_fuse<<<(6528 + 128 * 256 + THR - 1) / THR, THR>>>(Wcz, Wlz, blz, bcz,
                                                        Wcr, Wlr, blr, bcr,
                                                        Wch, Wlh, blh, bch);
    k_fuse2<<<(3 * KTOT * 128 + THR - 1) / THR, THR>>>(Wlh_bot);
    k_init<<<(NN * HH + THR - 1) / THR, THR>>>();

    // ---- fork: t=0 chain on main; t=1..11 interleaved per-t chains on s2 ----
    cudaEventRecord(evFork, 0);
    cudaStreamWaitEvent(s2, evFork, 0);

    k_deg_rng<<<(EE + THR - 1) / THR, THR>>>(ei, ea, 0, 1);
    k_dinv_rng<<<(NN + THR - 1) / THR, THR>>>(0, 1);
    k_aggself_rng<<<(NN + THR - 1) / THR, THR>>>(x_seq, 0, 1);
    k_scatter_one<<<(EE + THR - 1) / THR, THR>>>(ei, ea, x_seq, 0);

    const float* agg11 = agg_all + (size_t)11 * NN * FF;
    for (int t = 1; t < TT; ++t) {
        k_deg_rng<<<(EE + THR - 1) / THR, THR, 0, s2>>>(ei, ea, t, 1);
        k_dinv_rng<<<(NN + THR - 1) / THR, THR, 0, s2>>>(t, 1);
        k_aggself_rng<<<(NN + THR - 1) / THR, THR, 0, s2>>>(x_seq, t, 1);
        k_scatter_one<<<(EE + THR - 1) / THR, THR, 0, s2>>>(ei, ea, x_seq, t);
        cudaEventRecord(evT[t], s2);
    }
    k_transition<<<(NN * FF + THR - 1) / THR, THR, 0, s2>>>(agg11);
    cudaEventRecord(evTr, s2);

    dim3 gC((NN + 127) / 128);

    for (int t = 0; t < TT; ++t) {
        if (t > 0) cudaStreamWaitEvent(0, evT[t], 0);
        const float* aggt = agg_all + (size_t)t * NN * FF;
        int flags = (t == 11) ? 2 : 0;
        if (t == 0)
            k_cell<true><<<gC, THR_CELL, SMEM_CELL>>>(aggt, t, flags, hW, hb,
                                                      nullptr, nullptr);
        else
            k_cell<false><<<gC, THR_CELL, SMEM_CELL>>>(aggt, t, flags, hW, hb,
                                                       nullptr, nullptr);
    }

    cudaStreamWaitEvent(0, evTr, 0);
    const int* eiL = ei + (size_t)11 * 2 * EE;

    for (int k = 0; k < HOR; ++k) {
        const float* aggk = (k == 0) ? agg11 : (aggh + (size_t)(k & 1) * NN * FF);
        float* agghN = aggh + (size_t)((k + 1) & 1) * NN * FF;
        if (k > 0) {
            const float* predPrev = out + (size_t)(k - 1) * NN * OUTD;
            k_scatter3<<<(EE + THR - 1) / THR, THR>>>(
                eiL, predPrev, aggh + (size_t)(k & 1) * NN * FF);
        }
        k_cell<false><<<gC, THR_CELL, SMEM_CELL>>>(aggk, 11, 1, hW, hb,
                                                   out + (size_t)k * NN * OUTD, agghN);
    }
}

// round 17
// speedup vs baseline: 1.2016x; 1.0098x over previous
#include <cuda_runtime.h>
#include <cuda_bf16.h>
#include <math.h>

#define NN 50000
#define EE 1600000
#define TT 12
#define FF 16
#define HH 128
#define OUTD 3
#define HOR 6

#define KTOT 144            // 128 (h) + 16 (agg)
#define ASTRIDE 152         // bf16 units per row (304 B) -> conflict-free ldmatrix
#define ROWB (ASTRIDE * 2)  // 304 bytes

// smem layout (bytes)
#define OFF_AHI 0
#define OFF_ALO 38912
#define OFF_BHI 77824
#define OFF_BLO 116736
#define OFF_HS  155648      // hs fp32 [128][129]
#define SMEM_CELL (155648 + 128 * 129 * 4)   // 221696

#define THR_CELL 512

// ---------------- scratch ----------------
__device__ float g_dinv_all[TT * NN];
__device__ float g_agg_all[(size_t)TT * NN * FF];
__device__ float g_aggh[2 * NN * FF];
__device__ float g_nrm11[EE];
__device__ float g_h[NN * HH];
__device__ float g_hw[NN * HH];
__device__ unsigned char g_maskc[TT * NN];
__device__ unsigned char g_meff[TT * NN];
__device__ float g_Bzr_top[16 * 256];
__device__ float g_bzr[256];
__device__ float g_Bzr_bot[128 * 256];
__device__ float g_Bh_top[16 * 128];
__device__ float g_bh[128];
__device__ int g_isbyte;
// bf16 weight splits, [n][ASTRIDE] row-major (k contiguous), per gate {z,r,h}
__device__ __align__(16) unsigned short g_Bsp_hi[3][128 * ASTRIDE];
__device__ __align__(16) unsigned short g_Bsp_lo[3][128 * ASTRIDE];

// ---------------- helpers ----------------
__device__ __forceinline__ unsigned int s2u(const void* p) {
    unsigned int a;
    asm("{ .reg .u64 t; cvta.to.shared.u64 t, %1; cvt.u32.u64 %0, t; }"
        : "=r"(a) : "l"(p));
    return a;
}
__device__ __forceinline__ float bfr(float x) {
    return __bfloat162float(__float2bfloat16_rn(x));
}
__device__ __forceinline__ unsigned int pkbf(float lo, float hi) {  // lo -> low half
    unsigned int r;
    asm("cvt.rn.bf16x2.f32 %0, %1, %2;" : "=r"(r) : "f"(hi), "f"(lo));
    return r;
}
__device__ __forceinline__ void ldm4(unsigned int* r, unsigned int addr) {
    asm volatile("ldmatrix.sync.aligned.m8n8.x4.shared.b16 {%0,%1,%2,%3}, [%4];"
        : "=r"(r[0]), "=r"(r[1]), "=r"(r[2]), "=r"(r[3]) : "r"(addr));
}
__device__ __forceinline__ void mma_bf(float* d, const unsigned int* a,
                                       const unsigned int* b) {
    asm volatile(
        "mma.sync.aligned.m16n8k16.row.col.f32.bf16.bf16.f32 "
        "{%0,%1,%2,%3}, {%4,%5,%6,%7}, {%8,%9}, {%0,%1,%2,%3};"
        : "+f"(d[0]), "+f"(d[1]), "+f"(d[2]), "+f"(d[3])
        : "r"(a[0]), "r"(a[1]), "r"(a[2]), "r"(a[3]), "r"(b[0]), "r"(b[1]));
}
__device__ __forceinline__ float sigmoidf_(float v) {
    return __fdividef(1.0f, 1.0f + __expf(-v));
}
__device__ __forceinline__ float tanhf_(float v) {
    float e = __expf(2.0f * v);
    return 1.0f - __fdividef(2.0f, e + 1.0f);
}
#define CPA16(saddr, gptr) \
    asm volatile("cp.async.cg.shared.global [%0], [%1], 16;" \
                 :: "r"(saddr), "l"(gptr) : "memory")
#define CPA_COMMIT() asm volatile("cp.async.commit_group;" ::: "memory")
#define CPA_WAIT()   asm volatile("cp.async.wait_group 0;" ::: "memory")

__device__ __forceinline__ void stageB_async(unsigned int sbase, int gate, int tid) {
    const char* sh = (const char*)g_Bsp_hi[gate];
    const char* sl = (const char*)g_Bsp_lo[gate];
    unsigned int dh = sbase + OFF_BHI;
    unsigned int dl = sbase + OFF_BLO;
    for (int i = tid; i < 128 * ASTRIDE / 8; i += THR_CELL) {
        CPA16(dh + i * 16, sh + i * 16);
        CPA16(dl + i * 16, sl + i * 16);
    }
    CPA_COMMIT();
}

// ---------------- mask detection / conversion ----------------
__global__ void k_detect(const unsigned char* raw) {
    __shared__ int cnt;
    if (threadIdx.x == 0) cnt = 0;
    __syncthreads();
    int c = 0;
    for (int i = threadIdx.x; i < 4096; i += blockDim.x) c += (raw[i] != 0);
    atomicAdd(&cnt, c);
    __syncthreads();
    if (threadIdx.x == 0) g_isbyte = (cnt > 2048) ? 1 : 0;
}
__global__ void k_convert(const unsigned char* raw) {
    int n = blockIdx.x * blockDim.x + threadIdx.x;
    if (n >= NN) return;
    int isb = g_isbyte, seen = 0;
#pragma unroll
    for (int t = 0; t < TT; ++t) {
        int m = isb ? (raw[t * NN + n] != 0) : (((const int*)raw)[t * NN + n] != 0);
        g_maskc[t * NN + n] = (unsigned char)m;
        g_meff[t * NN + n] = (unsigned char)(m & seen);
        seen |= m;
    }
}

// ---------------- weight fusion ----------------
__global__ void k_fuse(const float* __restrict__ Wcz, const float* __restrict__ Wlz,
                       const float* __restrict__ blz, const float* __restrict__ bcz,
                       const float* __restrict__ Wcr, const float* __restrict__ Wlr,
                       const float* __restrict__ blr, const float* __restrict__ bcr,
                       const float* __restrict__ Wch, const float* __restrict__ Wlh,
                       const float* __restrict__ blh, const float* __restrict__ bch) {
    int i = blockIdx.x * blockDim.x + threadIdx.x;
    if (i < 16 * 256) {
        int k = i / 256, c = i % 256, cc = c & 127;
        const float* A = (c < 128) ? Wcz : Wcr;
        const float* B = (c < 128) ? Wlz : Wlr;
        float s = 0.f;
        for (int j = 0; j < 128; ++j) s += A[k * 128 + j] * B[j * 128 + cc];
        g_Bzr_top[i] = s;
    } else if (i < 4096 + 2048) {
        int r = i - 4096; int k = r / 128, c = r % 128;
        float s = 0.f;
        for (int j = 0; j < 128; ++j) s += Wch[k * 128 + j] * Wlh[j * 128 + c];
        g_Bh_top[r] = s;
    } else if (i < 6144 + 256) {
        int c = i - 6144; int cc = c & 127;
        const float* bc = (c < 128) ? bcz : bcr;
        const float* B  = (c < 128) ? Wlz : Wlr;
        const float* bl = (c < 128) ? blz : blr;
        float s = bl[cc];
        for (int j = 0; j < 128; ++j) s += bc[j] * B[j * 128 + cc];
        g_bzr[c] = s;
    } else if (i < 6400 + 128) {
        int c = i - 6400;
        float s = blh[c];
        for (int j = 0; j < 128; ++j) s += bch[j] * Wlh[j * 128 + c];
        g_bh[c] = s;
    } else if (i < 6528 + 128 * 256) {
        int r = i - 6528; int k = r / 256, c = r % 256;
        g_Bzr_bot[r] = (c < 128) ? Wlz[(128 + k) * 128 + c]
                                 : Wlr[(128 + k) * 128 + (c - 128)];
    }
}

__global__ void k_fuse2(const float* __restrict__ Wlh_bot) {
    int i = blockIdx.x * blockDim.x + threadIdx.x;
    if (i >= 3 * KTOT * 128) return;
    int g = i / (KTOT * 128), r = i - g * (KTOT * 128);
    int k = r / 128, n = r - k * 128;
    float w;
    if (k < 128) {
        if (g == 0)      w = g_Bzr_bot[k * 256 + n];
        else if (g == 1) w = g_Bzr_bot[k * 256 + 128 + n];
        else             w = Wlh_bot[k * 128 + n];
    } else {
        int kt = k - 128;
        if (g == 0)      w = g_Bzr_top[kt * 256 + n];
        else if (g == 1) w = g_Bzr_top[kt * 256 + 128 + n];
        else             w = g_Bh_top[kt * 128 + n];
    }
    float wh = bfr(w);
    g_Bsp_hi[g][n * ASTRIDE + k] = __bfloat16_as_ushort(__float2bfloat16_rn(wh));
    g_Bsp_lo[g][n * ASTRIDE + k] = __bfloat16_as_ushort(__float2bfloat16_rn(w - wh));
}

__global__ void k_init() {
    int i = blockIdx.x * blockDim.x + threadIdx.x;
    if (i < NN * HH) g_h[i] = 0.f;
    if (i < TT * NN) g_dinv_all[i] = 0.f;
}

// ---------------- degree / aggregation (t-ranged) ----------------
__global__ void k_deg_rng(const int* __restrict__ ei, const float* __restrict__ ea,
                          int t0, int nt) {
    int e = blockIdx.x * blockDim.x + threadIdx.x;
    if (e >= nt * EE) return;
    int t = t0 + e / EE, le = e % EE;
    int dst = __ldg(ei + (size_t)t * 2 * EE + EE + le);
    atomicAdd(&g_dinv_all[t * NN + dst], __ldg(ea + (size_t)t * EE + le));
}
__global__ void k_dinv_rng(int t0, int nt) {
    int i = blockIdx.x * blockDim.x + threadIdx.x;
    if (i >= nt * NN) return;
    int idx = t0 * NN + i;
    g_dinv_all[idx] = rsqrtf(g_dinv_all[idx] + 1.0f);
}
__global__ void k_aggself_rng(const float* __restrict__ x_seq, int t0, int nt) {
    int i = blockIdx.x * blockDim.x + threadIdx.x;
    if (i >= nt * NN) return;
    int t = t0 + i / NN, n = i % NN;
    float di = g_dinv_all[t * NN + n];
    float s = di * di;
    const float4* xp = (const float4*)(x_seq + (size_t)t * NN * FF + (size_t)n * FF);
    float4* op = (float4*)(g_agg_all + (size_t)t * NN * FF + (size_t)n * FF);
    float4 a = xp[0], b = xp[1], c = xp[2], d = xp[3];
    op[0] = make_float4(s * a.x, s * a.y, s * a.z, s * a.w);
    op[1] = make_float4(s * b.x, s * b.y, s * b.z, s * b.w);
    op[2] = make_float4(s * c.x, s * c.y, s * c.z, s * c.w);
    op[3] = make_float4(s * d.x, s * d.y, s * d.z, s * d.w);
}
#define REDV4(p, a, b, c, d)                                              \
    asm volatile("red.global.add.v4.f32 [%0], {%1,%2,%3,%4};"             \
                 :: "l"(p), "f"(a), "f"(b), "f"(c), "f"(d) : "memory")
__global__ void k_scatter_one(const int* __restrict__ ei, const float* __restrict__ ea,
                              const float* __restrict__ x_seq, int t) {
    int le = blockIdx.x * blockDim.x + threadIdx.x;
    if (le >= EE) return;
    const int* eit = ei + (size_t)t * 2 * EE;
    int s = __ldg(eit + le), d = __ldg(eit + EE + le);
    float ew = __ldg(ea + (size_t)t * EE + le);
    const float* dinv = g_dinv_all + t * NN;
    float nrm = dinv[s] * ew * dinv[d];
    if (t == 11) g_nrm11[le] = nrm;
    const float4* xp = (const float4*)(x_seq + (size_t)t * NN * FF + (size_t)s * FF);
    float4 a = xp[0], b = xp[1], c = xp[2], dd = xp[3];
    float* o = g_agg_all + (size_t)t * NN * FF + (size_t)d * FF;
    REDV4(o + 0,  nrm * a.x,  nrm * a.y,  nrm * a.z,  nrm * a.w);
    REDV4(o + 4,  nrm * b.x,  nrm * b.y,  nrm * b.z,  nrm * b.w);
    REDV4(o + 8,  nrm * c.x,  nrm * c.y,  nrm * c.z,  nrm * c.w);
    REDV4(o + 12, nrm * dd.x, nrm * dd.y, nrm * dd.z, nrm * dd.w);
}

// ---------------- fused TGCN cell: mma.sync bf16 split GEMMs ----------------
// HZ: h_eff known all-zero (t=0) -> only the agg k-tile contributes
// flags: bit0 = horizon, bit1 = write g_hw = mk ? hn : 0 (t==11)
template <bool HZ>
__global__ __launch_bounds__(THR_CELL, 1)
void k_cell(const float* __restrict__ agg, int t, int flags,
            const float* __restrict__ headW, const float* __restrict__ headb,
            float* __restrict__ outk, float* __restrict__ agghN) {
    extern __shared__ __align__(16) char smc[];
    char*  Ahi = smc + OFF_AHI;
    char*  Alo = smc + OFF_ALO;
    char*  Bhi = smc + OFF_BHI;
    float* hs  = (float*)(smc + OFF_HS);
    unsigned int sbase = s2u(smc);

    const int tid = threadIdx.x;
    const int nblk = blockIdx.x * 128;
    const bool horizon = (flags & 1) != 0;
    const bool wrHw = (flags & 2) != 0;
    const float* hsrc = horizon ? g_hw : g_h;
    const unsigned char* me = g_meff + (size_t)t * NN;
    const unsigned char* mk = g_maskc + (size_t)t * NN;

    const int w = tid >> 5, l = tid & 31;
    const int m0 = (w & 3) * 32, n0 = (w >> 2) * 32;
    const int fg = l >> 2, fc = l & 3;

    // ---- staging: B gate-z via cp.async; h+agg loads batched (MLP=9) ----
    stageB_async(sbase, 0, tid);
    {
        int row = tid >> 2, q = tid & 3;
        int nA = nblk + row;
        bool rowValid = nA < NN;
        bool rowOn = rowValid && (horizon || (me[nA] != 0));
        char* arow_h = Ahi + row * ROWB;
        char* arow_l = Alo + row * ROWB;

        // batch ALL independent global loads first
        float4 v[8], va;
        const float4* hp = (const float4*)(hsrc + (size_t)nA * HH + q * 32);
        const float4* ap = (const float4*)(agg + (size_t)nA * 16 + 4 * q);
        va = make_float4(0.f, 0.f, 0.f, 0.f);
        if (rowValid) va = __ldg(ap);
#pragma unroll
        for (int g8 = 0; g8 < 8; ++g8) {
            v[g8] = make_float4(0.f, 0.f, 0.f, 0.f);
            if (rowOn) v[g8] = __ldg(hp + g8);
        }
        // then split/store
#pragma unroll
        for (int g8 = 0; g8 < 8; ++g8) {
            int k0 = q * 32 + g8 * 4;
            hs[row * 129 + k0 + 0] = v[g8].x;
            hs[row * 129 + k0 + 1] = v[g8].y;
            hs[row * 129 + k0 + 2] = v[g8].z;
            hs[row * 129 + k0 + 3] = v[g8].w;
            float xh = bfr(v[g8].x), yh = bfr(v[g8].y);
            float zh = bfr(v[g8].z), wh = bfr(v[g8].w);
            *(unsigned int*)(arow_h + k0 * 2)     = pkbf(xh, yh);
            *(unsigned int*)(arow_h + k0 * 2 + 4) = pkbf(zh, wh);
            *(unsigned int*)(arow_l + k0 * 2)     = pkbf(v[g8].x - xh, v[g8].y - yh);
            *(unsigned int*)(arow_l + k0 * 2 + 4) = pkbf(v[g8].z - zh, v[g8].w - wh);
        }
        {
            int kb = (128 + q * 4) * 2;
            float xh = bfr(va.x), yh = bfr(va.y), zh = bfr(va.z), wh = bfr(va.w);
            *(unsigned int*)(arow_h + kb)     = pkbf(xh, yh);
            *(unsigned int*)(arow_h + kb + 4) = pkbf(zh, wh);
            *(unsigned int*)(arow_l + kb)     = pkbf(va.x - xh, va.y - yh);
            *(unsigned int*)(arow_l + kb + 4) = pkbf(va.z - zh, va.w - wh);
        }
    }
    CPA_WAIT();
    __syncthreads();

    unsigned int aHiAd = sbase + OFF_AHI + (m0 + (l & 15)) * ROWB + (l >> 4) * 16;
    unsigned int aLoAd = aHiAd + (OFF_ALO - OFF_AHI);
    unsigned int bHiAd = sbase + OFF_BHI +
                         (n0 + (l >> 4) * 8 + (l & 7)) * ROWB + ((l >> 3) & 1) * 16;
    unsigned int bLoAd = bHiAd + (OFF_BLO - OFF_BHI);

    float dd[32];
    float zreg[32];

#define MMA_KT(kt)                                                          \
    {                                                                       \
        unsigned int ah[2][4], al[2][4], bh[2][4], bl[2][4];                \
        ldm4(ah[0], aHiAd + (kt) * 32);                                     \
        ldm4(ah[1], aHiAd + (kt) * 32 + 16 * ROWB);                         \
        ldm4(al[0], aLoAd + (kt) * 32);                                     \
        ldm4(al[1], aLoAd + (kt) * 32 + 16 * ROWB);                         \
        ldm4(bh[0], bHiAd + (kt) * 32);                                     \
        ldm4(bh[1], bHiAd + (kt) * 32 + 16 * ROWB);                         \
        ldm4(bl[0], bLoAd + (kt) * 32);                                     \
        ldm4(bl[1], bLoAd + (kt) * 32 + 16 * ROWB);                         \
        _Pragma("unroll") for (int am = 0; am < 2; ++am)                    \
        _Pragma("unroll") for (int bn = 0; bn < 4; ++bn) {                  \
            float* dp = dd + (am * 4 + bn) * 4;                             \
            const unsigned int* bhp = &bh[bn >> 1][(bn & 1) * 2];           \
            const unsigned int* blp = &bl[bn >> 1][(bn & 1) * 2];           \
            mma_bf(dp, ah[am], bhp);                                        \
            mma_bf(dp, ah[am], blp);                                        \
            mma_bf(dp, al[am], bhp);                                        \
        }                                                                   \
    }

#define GATE_MMA()                                                          \
    _Pragma("unroll") for (int j = 0; j < 32; ++j) dd[j] = 0.f;             \
    if (HZ) { MMA_KT(8); }                                                  \
    else {                                                                  \
        _Pragma("unroll")                                                   \
        for (int kt = 0; kt < 9; ++kt) { MMA_KT(kt); }                      \
    }

    // ================= gate Z =================
    GATE_MMA();
    __syncthreads();                     // all warps done with B(z)
    stageB_async(sbase, 1, tid);         // prefetch B(r) under z epilogue
#pragma unroll
    for (int am = 0; am < 2; ++am)
#pragma unroll
    for (int bn = 0; bn < 4; ++bn)
#pragma unroll
    for (int e = 0; e < 4; ++e) {
        int idx = (am * 4 + bn) * 4 + e;
        int col = n0 + 8 * bn + 2 * fc + (e & 1);
        zreg[idx] = sigmoidf_(dd[idx] + g_bzr[col]);
    }
    CPA_WAIT();
    __syncthreads();

    // ================= gate R =================
    GATE_MMA();
    __syncthreads();                     // all warps done with B(r) and A
    stageB_async(sbase, 2, tid);         // prefetch B(h) under hr epilogue
#pragma unroll
    for (int am = 0; am < 2; ++am)
#pragma unroll
    for (int bn = 0; bn < 4; ++bn)
#pragma unroll
    for (int eh = 0; eh < 2; ++eh) {
        int idx = (am * 4 + bn) * 4 + eh * 2;
        int row = m0 + 16 * am + fg + eh * 8;
        int cb = n0 + 8 * bn + 2 * fc;
        float r0 = sigmoidf_(dd[idx]     + g_bzr[128 + cb]);
        float r1 = sigmoidf_(dd[idx + 1] + g_bzr[128 + cb + 1]);
        if (!HZ) {
            float p0 = hs[row * 129 + cb] * r0;
            float p1 = hs[row * 129 + cb + 1] * r1;
            float p0h = bfr(p0), p1h = bfr(p1);
            *(unsigned int*)(Ahi + row * ROWB + cb * 2) = pkbf(p0h, p1h);
            *(unsigned int*)(Alo + row * ROWB + cb * 2) = pkbf(p0 - p0h, p1 - p1h);
        }
    }
    CPA_WAIT();
    __syncthreads();

    // ================= gate H + combine =================
    GATE_MMA();
#pragma unroll
    for (int am = 0; am < 2; ++am)
#pragma unroll
    for (int bn = 0; bn < 4; ++bn)
#pragma unroll
    for (int e = 0; e < 4; ++e) {
        int idx = (am * 4 + bn) * 4 + e;
        int row = m0 + 16 * am + fg + (e >> 1) * 8;
        int col = n0 + 8 * bn + 2 * fc + (e & 1);
        float ht = tanhf_(dd[idx] + g_bh[col]);
        float z = zreg[idx];
        float h0 = hs[row * 129 + col];
        hs[row * 129 + col] = ht + z * (h0 - ht);   // == z*h0 + (1-z)*ht
    }
    __syncthreads();

    if (horizon && tid < 96) {
        float4 wv = *(const float4*)(headW + tid * 4);
        ((float*)Bhi)[tid * 4 + 0] = wv.x; ((float*)Bhi)[tid * 4 + 1] = wv.y;
        ((float*)Bhi)[tid * 4 + 2] = wv.z; ((float*)Bhi)[tid * 4 + 3] = wv.w;
    }

    // ---- coalesced masked writeback ----
    {
        int row = tid >> 2, cg = (tid & 3) * 32;
        int n = nblk + row;
        if (n < NN) {
            bool wr = horizon ? true : (mk[n] != 0);
#pragma unroll
            for (int i4 = 0; i4 < 8; ++i4) {
                float4 v;
                v.x = hs[row * 129 + cg + 4 * i4 + 0];
                v.y = hs[row * 129 + cg + 4 * i4 + 1];
                v.z = hs[row * 129 + cg + 4 * i4 + 2];
                v.w = hs[row * 129 + cg + 4 * i4 + 3];
                if (horizon) {
                    *(float4*)(g_hw + (size_t)n * HH + cg + 4 * i4) = v;
                } else {
                    if (wr) *(float4*)(g_h + (size_t)n * HH + cg + 4 * i4) = v;
                    if (wrHw) {
                        float4 vz = wr ? v : make_float4(0.f, 0.f, 0.f, 0.f);
                        *(float4*)(g_hw + (size_t)n * HH + cg + 4 * i4) = vz;
                    }
                }
            }
        }
    }

    // ---- fused head prediction (horizon): 4 threads per node + shfl reduce ----
    if (horizon) {
        __syncthreads();
        int row = tid >> 2, pp = tid & 3;
        int n = nblk + row;
        const float* hwv = (const float*)Bhi;
        float p0 = 0.f, p1 = 0.f, p2 = 0.f;
        int c0 = pp * 32;
#pragma unroll 8
        for (int c = c0; c < c0 + 32; ++c) {
            float hv = hs[row * 129 + c];
            p0 += hv * hwv[c * 3 + 0];
            p1 += hv * hwv[c * 3 + 1];
            p2 += hv * hwv[c * 3 + 2];
        }
#pragma unroll
        for (int o = 2; o >= 1; o >>= 1) {
            p0 += __shfl_down_sync(0xFFFFFFFFu, p0, o, 4);
            p1 += __shfl_down_sync(0xFFFFFFFFu, p1, o, 4);
            p2 += __shfl_down_sync(0xFFFFFFFFu, p2, o, 4);
        }
        if (pp == 0 && n < NN) {
            p0 += headb[0]; p1 += headb[1]; p2 += headb[2];
            outk[n * 3 + 0] = p0;
            outk[n * 3 + 1] = p1;
            outk[n * 3 + 2] = p2;
            float di = g_dinv_all[11 * NN + n];
            float s = di * di;
            agghN[n * FF + 0] = s * p0;
            agghN[n * FF + 1] = s * p1;
            agghN[n * FF + 2] = s * p2;
        }
    }
}

// ---------------- transition / horizon helpers ----------------
__global__ void k_transition(const float* __restrict__ agg11) {
    int i = blockIdx.x * blockDim.x + threadIdx.x;
    if (i >= NN * FF) return;
    if ((i & 15) < 3) return;
    float v = agg11[i];
    g_aggh[i] = v;
    g_aggh[NN * FF + i] = v;
}
__global__ void k_scatter3(const int* __restrict__ ei11,
                           const float* __restrict__ pred,
                           float* __restrict__ target) {
    int e = blockIdx.x * blockDim.x + threadIdx.x;
    if (e >= EE) return;
    int s = __ldg(ei11 + e), d = __ldg(ei11 + EE + e);
    float nrm = __ldg(g_nrm11 + e);
    float p0 = pred[s * 3 + 0], p1 = pred[s * 3 + 1], p2 = pred[s * 3 + 2];
    float* o = target + (size_t)d * FF;
    REDV4(o, nrm * p0, nrm * p1, nrm * p2, 0.f);   // col3 += 0 (frozen col, inert)
}

// ---------------- launch ----------------
extern "C" void kernel_launch(void* const* d_in, const int* in_sizes, int n_in,
                              void* d_out, int out_size) {
    const float* x_seq = (const float*)d_in[0];
    const int*   ei    = (const int*)d_in[1];
    const float* ea    = (const float*)d_in[2];
    const unsigned char* mraw = (const unsigned char*)d_in[3];
    const float* Wcz = (const float*)d_in[4];
    const float* bcz = (const float*)d_in[5];
    const float* Wlz = (const float*)d_in[6];
    const float* blz = (const float*)d_in[7];
    const float* Wcr = (const float*)d_in[8];
    const float* bcr = (const float*)d_in[9];
    const float* Wlr = (const float*)d_in[10];
    const float* blr = (const float*)d_in[11];
    const float* Wch = (const float*)d_in[12];
    const float* bch = (const float*)d_in[13];
    const float* Wlh = (const float*)d_in[14];
    const float* blh = (const float*)d_in[15];
    const float* hW  = (const float*)d_in[16];
    const float* hb  = (const float*)d_in[17];
    float* out = (float*)d_out;

    void* p;
    cudaGetSymbolAddress(&p, g_agg_all);
    const float* agg_all = (const float*)p;
    cudaGetSymbolAddress(&p, g_aggh);
    float* aggh = (float*)p;

    static int s_init_done = 0;
    static cudaStream_t s2;
    static cudaEvent_t evFork;
    static cudaEvent_t evT[TT];
    static cudaEvent_t evTr;
    if (!s_init_done) {
        cudaFuncSetAttribute(k_cell<false>,
                             cudaFuncAttributeMaxDynamicSharedMemorySize, SMEM_CELL);
        cudaFuncSetAttribute(k_cell<true>,
                             cudaFuncAttributeMaxDynamicSharedMemorySize, SMEM_CELL);
        cudaStreamCreateWithFlags(&s2, cudaStreamNonBlocking);
        cudaEventCreateWithFlags(&evFork, cudaEventDisableTiming);
        cudaEventCreateWithFlags(&evTr, cudaEventDisableTiming);
        for (int t = 0; t < TT; ++t)
            cudaEventCreateWithFlags(&evT[t], cudaEventDisableTiming);
        s_init_done = 1;
    }

    const int THR = 256;
    const float* Wlh_bot = Wlh + 128 * 128;

    // ---- shared prologue (main) ----
    k_detect<<<1, THR>>>(mraw);
    k_convert<<<(NN + THR - 1) / THR, THR>>>(mraw);
    k_fuse<<<(6528 + 128 * 256 + THR - 1) / THR, THR>>>(Wcz, Wlz, blz, bcz,
                                                        Wcr, Wlr, blr, bcr,
                                                        Wch, Wlh, blh, bch);
    k_fuse2<<<(3 * KTOT * 128 + THR - 1) / THR, THR>>>(Wlh_bot);
    k_init<<<(NN * HH + THR - 1) / THR, THR>>>();

    // ---- fork: t=0 chain on main; t=1..11 interleaved per-t chains on s2 ----
    cudaEventRecord(evFork, 0);
    cudaStreamWaitEvent(s2, evFork, 0);

    k_deg_rng<<<(EE + THR - 1) / THR, THR>>>(ei, ea, 0, 1);
    k_dinv_rng<<<(NN + THR - 1) / THR, THR>>>(0, 1);
    k_aggself_rng<<<(NN + THR - 1) / THR, THR>>>(x_seq, 0, 1);
    k_scatter_one<<<(EE + THR - 1) / THR, THR>>>(ei, ea, x_seq, 0);

    const float* agg11 = agg_all + (size_t)11 * NN * FF;
    for (int t = 1; t < TT; ++t) {
        k_deg_rng<<<(EE + THR - 1) / THR, THR, 0, s2>>>(ei, ea, t, 1);
        k_dinv_rng<<<(NN + THR - 1) / THR, THR, 0, s2>>>(t, 1);
        k_aggself_rng<<<(NN + THR - 1) / THR, THR, 0, s2>>>(x_seq, t, 1);
        k_scatter_one<<<(EE + THR - 1) / THR, THR, 0, s2>>>(ei, ea, x_seq, t);
        cudaEventRecord(evT[t], s2);
    }
    k_transition<<<(NN * FF + THR - 1) / THR, THR, 0, s2>>>(agg11);
    cudaEventRecord(evTr, s2);

    dim3 gC((NN + 127) / 128);

    for (int t = 0; t < TT; ++t) {
        if (t > 0) cudaStreamWaitEvent(0, evT[t], 0);
        const float* aggt = agg_all + (size_t)t * NN * FF;
        int flags = (t == 11) ? 2 : 0;
        if (t == 0)
            k_cell<true><<<gC, THR_CELL, SMEM_CELL>>>(aggt, t, flags, hW, hb,
                                                      nullptr, nullptr);
        else
            k_cell<false><<<gC, THR_CELL, SMEM_CELL>>>(aggt, t, flags, hW, hb,
                                                       nullptr, nullptr);
    }

    cudaStreamWaitEvent(0, evTr, 0);
    const int* eiL = ei + (size_t)11 * 2 * EE;

    for (int k = 0; k < HOR; ++k) {
        const float* aggk = (k == 0) ? agg11 : (aggh + (size_t)(k & 1) * NN * FF);
        float* agghN = aggh + (size_t)((k + 1) & 1) * NN * FF;
        if (k > 0) {
            const float* predPrev = out + (size_t)(k - 1) * NN * OUTD;
            k_scatter3<<<(EE + THR - 1) / THR, THR>>>(
                eiL, predPrev, aggh + (size_t)(k & 1) * NN * FF);
        }
        k_cell<false><<<gC, THR_CELL, SMEM_CELL>>>(aggk, 11, 1, hW, hb,
                                                   out + (size_t)k * NN * OUTD, agghN);
    }
}